// round 1
// baseline (speedup 1.0000x reference)
#include <cuda_runtime.h>
#include <math.h>
#include <stdint.h>

// ---------------- problem constants ----------------
#define BB   4
#define SS   1024
#define HH   1024
#define NHH  16
#define HDD  64
#define FFF  4096
#define ADD  256
#define MM   (BB*SS)          // 4096 rows
#define EPSF 1e-5f

// ---------------- scratch (__device__ globals; no cudaMalloc allowed) ----------------
__device__ float g_q  [MM*HH];
__device__ float g_k  [MM*HH];
__device__ float g_v  [MM*HH];
__device__ float g_ctx[MM*HH];
__device__ float g_att[MM*HH];
__device__ float g_h  [MM*HH];
__device__ float g_ff1[(size_t)MM*FFF];
__device__ float g_ff2[MM*HH];
__device__ float g_ad1[MM*ADD];
__device__ float g_ad2[MM*HH];
__device__ float g_gate[BB*NHH*SS];
__device__ float g_pb  [NHH*2048];    // [h][d], d = rel + 1023

// ---------------- relative position bias table ----------------
__global__ void pbias_kernel(const float* __restrict__ rel_embed, float* __restrict__ pb)
{
    int d = blockIdx.x * blockDim.x + threadIdx.x;
    if (d >= 2047) return;
    int rel = d - 1023;                      // rel = j - i
    int bucket = (rel > 0) ? 160 : 0;
    int r = rel < 0 ? -rel : rel;
    int val;
    if (r < 80) {
        val = r;
    } else {
        float rf = (float)(r < 1 ? 1 : r);
        float t = logf(rf / 80.0f) / 2.3025851f * 80.0f;   // log(800/80)=log(10)
        int large = 80 + (int)t;
        val = large < 159 ? large : 159;
    }
    bucket += val;
    #pragma unroll
    for (int h = 0; h < NHH; h++)
        pb[h * 2048 + d] = rel_embed[bucket * NHH + h];
}

// ---------------- gate kernel: gate_out[b,h,s] ----------------
__global__ void gate_kernel(const float* __restrict__ x, const float* __restrict__ Wg,
                            const float* __restrict__ bg, const float* __restrict__ gc,
                            float* __restrict__ gate)
{
    __shared__ float xs[HH];
    int bs = blockIdx.x;                 // b*S + s
    int t = threadIdx.x;                 // 128 threads
    for (int i = t; i < HH; i += 128) xs[i] = x[(size_t)bs * HH + i];
    __syncthreads();
    int h = t >> 3, e = t & 7;
    float acc = bg[e];
    const float* wrow = Wg + e * HDD;
    const float* xrow = xs + h * HDD;
    #pragma unroll 8
    for (int d = 0; d < HDD; d++) acc += xrow[d] * wrow[d];
    // sum groups of 4 e's
    acc += __shfl_xor_sync(0xffffffffu, acc, 1);
    acc += __shfl_xor_sync(0xffffffffu, acc, 2);
    float other = __shfl_xor_sync(0xffffffffu, acc, 4);
    if (e == 0) {
        float p0 = acc, p1 = other;
        float ga = 1.0f / (1.0f + expf(-p0));
        float gb = 1.0f / (1.0f + expf(-p1));
        float go = ga * (gb * gc[h] - 1.0f) + 2.0f;
        int b = bs >> 10, s = bs & 1023;
        gate[(b * NHH + h) * SS + s] = go;
    }
}

// ---------------- tiled SGEMM: C[M,N] = A[M,K] @ W[N,K]^T + bias, epilogue ----------------
// BM=BN=128, BK=16, 256 threads, 8x8 per thread. M%128==0, N%128==0, K%16==0.
template<int EPI>   // 0=none, 1=gelu(exact), 2=elu
__global__ void gemm_bias(const float* __restrict__ A, const float* __restrict__ W,
                          const float* __restrict__ bias, float* __restrict__ C,
                          int M, int N, int K)
{
    __shared__ float As[16][128];
    __shared__ float Bs[16][128];
    int t  = threadIdx.x;
    int tx = t & 15, ty = t >> 4;
    int bm = blockIdx.y * 128, bn = blockIdx.x * 128;

    float acc[8][8];
    #pragma unroll
    for (int i = 0; i < 8; i++)
        #pragma unroll
        for (int j = 0; j < 8; j++) acc[i][j] = 0.0f;

    int lr = t >> 2;             // 0..63
    int lc = (t & 3) * 4;        // 0,4,8,12
    const float* Ap = A + (size_t)(bm + lr) * K + lc;
    const float* Wp = W + (size_t)(bn + lr) * K + lc;

    for (int k0 = 0; k0 < K; k0 += 16) {
        float4 a0 = *(const float4*)(Ap);
        float4 a1 = *(const float4*)(Ap + (size_t)64 * K);
        float4 b0 = *(const float4*)(Wp);
        float4 b1 = *(const float4*)(Wp + (size_t)64 * K);
        As[lc+0][lr]    = a0.x; As[lc+1][lr]    = a0.y; As[lc+2][lr]    = a0.z; As[lc+3][lr]    = a0.w;
        As[lc+0][lr+64] = a1.x; As[lc+1][lr+64] = a1.y; As[lc+2][lr+64] = a1.z; As[lc+3][lr+64] = a1.w;
        Bs[lc+0][lr]    = b0.x; Bs[lc+1][lr]    = b0.y; Bs[lc+2][lr]    = b0.z; Bs[lc+3][lr]    = b0.w;
        Bs[lc+0][lr+64] = b1.x; Bs[lc+1][lr+64] = b1.y; Bs[lc+2][lr+64] = b1.z; Bs[lc+3][lr+64] = b1.w;
        __syncthreads();
        #pragma unroll
        for (int kk = 0; kk < 16; kk++) {
            float4 av0 = *(float4*)&As[kk][ty*8];
            float4 av1 = *(float4*)&As[kk][ty*8+4];
            float4 bv0 = *(float4*)&Bs[kk][tx*8];
            float4 bv1 = *(float4*)&Bs[kk][tx*8+4];
            float a[8] = {av0.x,av0.y,av0.z,av0.w,av1.x,av1.y,av1.z,av1.w};
            float b[8] = {bv0.x,bv0.y,bv0.z,bv0.w,bv1.x,bv1.y,bv1.z,bv1.w};
            #pragma unroll
            for (int i = 0; i < 8; i++)
                #pragma unroll
                for (int j = 0; j < 8; j++)
                    acc[i][j] += a[i] * b[j];
        }
        __syncthreads();
        Ap += 16; Wp += 16;
    }

    #pragma unroll
    for (int i = 0; i < 8; i++) {
        int m = bm + ty*8 + i;
        float* crow = C + (size_t)m * N + bn + tx*8;
        float r[8];
        #pragma unroll
        for (int j = 0; j < 8; j++) {
            float v = acc[i][j] + bias[bn + tx*8 + j];
            if (EPI == 1) v = 0.5f * v * (1.0f + erff(v * 0.7071067811865476f));
            else if (EPI == 2) v = v > 0.0f ? v : expm1f(v);
            r[j] = v;
        }
        *(float4*)(crow)     = *(float4*)(r);
        *(float4*)(crow + 4) = *(float4*)(r + 4);
    }
}

// ---------------- flash attention, 64x64 tiles, fp32 ----------------
// grid (S/64, NH, B), 256 threads (tx:16, ty:16). Each thread: 4 rows x 4 cols.
__global__ void attn_kernel(const float* __restrict__ q, const float* __restrict__ k,
                            const float* __restrict__ v, const float* __restrict__ gate,
                            const float* __restrict__ pb, float* __restrict__ ctx)
{
    __shared__ float Qs [64][64];
    __shared__ float KPs[64][64];   // K^T during score, then P
    __shared__ float Vs [64][64];
    int t  = threadIdx.x;
    int tx = t & 15, ty = t >> 4;
    int i0 = blockIdx.x * 64;
    int h  = blockIdx.y;
    int b  = blockIdx.z;

    // load Q tile: Qs[row][d]
    for (int idx = t; idx < 64*16; idx += 256) {
        int r = idx >> 4, c4 = (idx & 15) << 2;
        *(float4*)&Qs[r][c4] =
            *(const float4*)(q + ((size_t)(b*SS + i0 + r)) * HH + h*HDD + c4);
    }

    float gate_i[4];
    #pragma unroll
    for (int ii = 0; ii < 4; ii++)
        gate_i[ii] = gate[(b*NHH + h) * SS + i0 + ty*4 + ii];

    float m_run[4], l_run[4], acc[4][4];
    #pragma unroll
    for (int ii = 0; ii < 4; ii++) {
        m_run[ii] = -INFINITY; l_run[ii] = 0.0f;
        #pragma unroll
        for (int c = 0; c < 4; c++) acc[ii][c] = 0.0f;
    }

    const float* pbh = pb + h * 2048;

    for (int j0 = 0; j0 < SS; j0 += 64) {
        __syncthreads();   // protect KPs/Vs from previous PV reads
        for (int idx = t; idx < 64*16; idx += 256) {
            int r = idx >> 4, c4 = (idx & 15) << 2;
            float4 kv = *(const float4*)(k + ((size_t)(b*SS + j0 + r)) * HH + h*HDD + c4);
            KPs[c4+0][r] = kv.x; KPs[c4+1][r] = kv.y; KPs[c4+2][r] = kv.z; KPs[c4+3][r] = kv.w;
            *(float4*)&Vs[r][c4] =
                *(const float4*)(v + ((size_t)(b*SS + j0 + r)) * HH + h*HDD + c4);
        }
        __syncthreads();

        // scores: S = Q K^T
        float s[4][4];
        #pragma unroll
        for (int ii = 0; ii < 4; ii++)
            #pragma unroll
            for (int jj = 0; jj < 4; jj++) s[ii][jj] = 0.0f;
        #pragma unroll 8
        for (int kk = 0; kk < 64; kk++) {
            float4 k4 = *(float4*)&KPs[kk][tx*4];
            #pragma unroll
            for (int ii = 0; ii < 4; ii++) {
                float qv = Qs[ty*4 + ii][kk];
                s[ii][0] += qv * k4.x; s[ii][1] += qv * k4.y;
                s[ii][2] += qv * k4.z; s[ii][3] += qv * k4.w;
            }
        }
        // scale + gated relative bias
        #pragma unroll
        for (int ii = 0; ii < 4; ii++) {
            int ig = i0 + ty*4 + ii;
            #pragma unroll
            for (int jj = 0; jj < 4; jj++) {
                int jg = j0 + tx*4 + jj;
                s[ii][jj] = s[ii][jj] * 0.125f + gate_i[ii] * pbh[jg - ig + 1023];
            }
        }
        // online softmax
        #pragma unroll
        for (int ii = 0; ii < 4; ii++) {
            float mt = fmaxf(fmaxf(s[ii][0], s[ii][1]), fmaxf(s[ii][2], s[ii][3]));
            #pragma unroll
            for (int off = 8; off >= 1; off >>= 1)
                mt = fmaxf(mt, __shfl_xor_sync(0xffffffffu, mt, off));
            float mn = fmaxf(m_run[ii], mt);
            float alpha = expf(m_run[ii] - mn);
            float ls = 0.0f;
            #pragma unroll
            for (int jj = 0; jj < 4; jj++) {
                float p = expf(s[ii][jj] - mn);
                s[ii][jj] = p; ls += p;
            }
            #pragma unroll
            for (int off = 8; off >= 1; off >>= 1)
                ls += __shfl_xor_sync(0xffffffffu, ls, off);
            l_run[ii] = l_run[ii] * alpha + ls;
            m_run[ii] = mn;
            #pragma unroll
            for (int c = 0; c < 4; c++) acc[ii][c] *= alpha;
        }
        __syncthreads();   // done reading KPs as K
        #pragma unroll
        for (int ii = 0; ii < 4; ii++)
            *(float4*)&KPs[ty*4 + ii][tx*4] = make_float4(s[ii][0], s[ii][1], s[ii][2], s[ii][3]);
        __syncthreads();
        // acc += P V
        #pragma unroll 8
        for (int jj = 0; jj < 64; jj++) {
            float4 v4 = *(float4*)&Vs[jj][tx*4];
            #pragma unroll
            for (int ii = 0; ii < 4; ii++) {
                float p = KPs[ty*4 + ii][jj];
                acc[ii][0] += p * v4.x; acc[ii][1] += p * v4.y;
                acc[ii][2] += p * v4.z; acc[ii][3] += p * v4.w;
            }
        }
    }

    #pragma unroll
    for (int ii = 0; ii < 4; ii++) {
        float inv = 1.0f / l_run[ii];
        float4 o = make_float4(acc[ii][0]*inv, acc[ii][1]*inv, acc[ii][2]*inv, acc[ii][3]*inv);
        *(float4*)(ctx + ((size_t)(b*SS + i0 + ty*4 + ii)) * HH + h*HDD + tx*4) = o;
    }
}

// ---------------- residual-add + LayerNorm (2 or 3 way add) ----------------
__global__ void ln_kernel(const float* __restrict__ A, const float* __restrict__ B,
                          const float* __restrict__ C,   // may be null
                          const float* __restrict__ g, const float* __restrict__ bt,
                          float* __restrict__ out)
{
    __shared__ float sm[8];
    int row = blockIdx.x;
    int t = threadIdx.x;                 // 256
    size_t base = (size_t)row * HH;
    float vals[4];
    #pragma unroll
    for (int u = 0; u < 4; u++) {
        int i = t + u*256;
        float v = A[base + i] + B[base + i];
        if (C) v += C[base + i];
        vals[u] = v;
    }
    // mean
    float sum = vals[0] + vals[1] + vals[2] + vals[3];
    #pragma unroll
    for (int off = 16; off >= 1; off >>= 1) sum += __shfl_xor_sync(0xffffffffu, sum, off);
    if ((t & 31) == 0) sm[t >> 5] = sum;
    __syncthreads();
    float tot = 0.0f;
    #pragma unroll
    for (int w = 0; w < 8; w++) tot += sm[w];
    float mean = tot * (1.0f / HH);
    __syncthreads();
    // variance
    float vs = 0.0f;
    #pragma unroll
    for (int u = 0; u < 4; u++) { float d = vals[u] - mean; vs += d * d; }
    #pragma unroll
    for (int off = 16; off >= 1; off >>= 1) vs += __shfl_xor_sync(0xffffffffu, vs, off);
    if ((t & 31) == 0) sm[t >> 5] = vs;
    __syncthreads();
    float vtot = 0.0f;
    #pragma unroll
    for (int w = 0; w < 8; w++) vtot += sm[w];
    float rstd = rsqrtf(vtot * (1.0f / HH) + EPSF);
    #pragma unroll
    for (int u = 0; u < 4; u++) {
        int i = t + u*256;
        out[base + i] = (vals[u] - mean) * rstd * g[i] + bt[i];
    }
}

// ---------------- launch ----------------
extern "C" void kernel_launch(void* const* d_in, const int* in_sizes, int n_in,
                              void* d_out, int out_size)
{
    const float* x   = (const float*)d_in[0];
    const float* Wq  = (const float*)d_in[1];
    const float* bq  = (const float*)d_in[2];
    const float* Wk  = (const float*)d_in[3];
    const float* bk  = (const float*)d_in[4];
    const float* Wv  = (const float*)d_in[5];
    const float* bv  = (const float*)d_in[6];
    const float* Wo  = (const float*)d_in[7];
    const float* bo  = (const float*)d_in[8];
    const float* Wg  = (const float*)d_in[9];
    const float* bg  = (const float*)d_in[10];
    const float* gru = (const float*)d_in[11];
    const float* rel = (const float*)d_in[12];
    const float* l1g = (const float*)d_in[13];
    const float* l1b = (const float*)d_in[14];
    const float* W1  = (const float*)d_in[15];
    const float* b1  = (const float*)d_in[16];
    const float* W2  = (const float*)d_in[17];
    const float* b2  = (const float*)d_in[18];
    const float* l2g = (const float*)d_in[19];
    const float* l2b = (const float*)d_in[20];
    const float* Wad = (const float*)d_in[21];
    const float* bad = (const float*)d_in[22];
    const float* Wau = (const float*)d_in[23];
    const float* bau = (const float*)d_in[24];
    float* out = (float*)d_out;

    float *pq, *pk, *pv, *pctx, *patt, *ph, *pff1, *pff2, *pad1, *pad2, *pgate, *ppb;
    cudaGetSymbolAddress((void**)&pq,   g_q);
    cudaGetSymbolAddress((void**)&pk,   g_k);
    cudaGetSymbolAddress((void**)&pv,   g_v);
    cudaGetSymbolAddress((void**)&pctx, g_ctx);
    cudaGetSymbolAddress((void**)&patt, g_att);
    cudaGetSymbolAddress((void**)&ph,   g_h);
    cudaGetSymbolAddress((void**)&pff1, g_ff1);
    cudaGetSymbolAddress((void**)&pff2, g_ff2);
    cudaGetSymbolAddress((void**)&pad1, g_ad1);
    cudaGetSymbolAddress((void**)&pad2, g_ad2);
    cudaGetSymbolAddress((void**)&pgate, g_gate);
    cudaGetSymbolAddress((void**)&ppb,  g_pb);

    // 1) relative position bias table
    pbias_kernel<<<(2047 + 127) / 128, 128>>>(rel, ppb);
    // 2) gates
    gate_kernel<<<BB * SS, 128>>>(x, Wg, bg, gru, pgate);
    // 3) QKV projections
    gemm_bias<0><<<dim3(HH/128, MM/128), 256>>>(x, Wq, bq, pq, MM, HH, HH);
    gemm_bias<0><<<dim3(HH/128, MM/128), 256>>>(x, Wk, bk, pk, MM, HH, HH);
    gemm_bias<0><<<dim3(HH/128, MM/128), 256>>>(x, Wv, bv, pv, MM, HH, HH);
    // 4) attention
    attn_kernel<<<dim3(SS/64, NHH, BB), 256>>>(pq, pk, pv, pgate, ppb, pctx);
    // 5) output projection
    gemm_bias<0><<<dim3(HH/128, MM/128), 256>>>(pctx, Wo, bo, patt, MM, HH, HH);
    // 6) residual + LN1
    ln_kernel<<<MM, 256>>>(x, patt, nullptr, l1g, l1b, ph);
    // 7) FFN
    gemm_bias<1><<<dim3(FFF/128, MM/128), 256>>>(ph, W1, b1, pff1, MM, FFF, HH);
    gemm_bias<0><<<dim3(HH/128, MM/128), 256>>>(pff1, W2, b2, pff2, MM, HH, FFF);
    // 8) adapter
    gemm_bias<2><<<dim3(ADD/128, MM/128), 256>>>(ph, Wad, bad, pad1, MM, ADD, HH);
    gemm_bias<0><<<dim3(HH/128, MM/128), 256>>>(pad1, Wau, bau, pad2, MM, HH, ADD);
    // 9) h + ff + adapt, LN2 -> out
    ln_kernel<<<MM, 256>>>(ph, pff2, pad2, l2g, l2b, out);
}

// round 3
// speedup vs baseline: 2.2922x; 2.2922x over previous
#include <cuda_runtime.h>
#include <math.h>
#include <stdint.h>

// ---------------- problem constants ----------------
#define BB   4
#define SS   1024
#define HH   1024
#define NHH  16
#define HDD  64
#define FFF  4096
#define ADD  256
#define MM   (BB*SS)          // 4096 rows
#define EPSF 1e-5f

// ---------------- scratch ----------------
__device__ float g_q  [MM*HH];
__device__ float g_k  [MM*HH];
__device__ float g_v  [MM*HH];
__device__ float g_ctx[MM*HH];
__device__ float g_att[MM*HH];
__device__ float g_h  [MM*HH];
__device__ float g_ff1[(size_t)MM*FFF];
__device__ float g_ff2[MM*HH];
__device__ float g_ad1[MM*ADD];
__device__ float g_ad2[MM*HH];
__device__ float g_gate[BB*NHH*SS];
__device__ float g_pb  [NHH*2048];

// ---------------- helpers ----------------
__device__ __forceinline__ uint32_t f2tf32(float x) {
    uint32_t u;
    asm("cvt.rna.tf32.f32 %0, %1;" : "=r"(u) : "f"(x));
    return u;
}

__device__ __forceinline__ void mma_tf32(float& c0, float& c1, float& c2, float& c3,
                                         uint32_t a0, uint32_t a1, uint32_t a2, uint32_t a3,
                                         uint32_t b0, uint32_t b1) {
    asm volatile(
        "mma.sync.aligned.m16n8k8.row.col.f32.tf32.tf32.f32 "
        "{%0,%1,%2,%3}, {%4,%5,%6,%7}, {%8,%9}, {%0,%1,%2,%3};\n"
        : "+f"(c0), "+f"(c1), "+f"(c2), "+f"(c3)
        : "r"(a0), "r"(a1), "r"(a2), "r"(a3), "r"(b0), "r"(b1));
}

// ================= mma.sync tf32 GEMM =================
// C[M,N] = A[M,K] @ W[N,K]^T + bias, epilogue.
// BM=BN=128, BK=32. 256 threads = 8 warps, warp grid 2(m) x 4(n),
// warp tile 64x32 -> 4 m-tiles (m16) x 4 n-tiles (n8), k8 steps.
// Smem: double-buffered, stride 36 words (conflict-free fragment loads).
#define GS_STRIDE 36
#define GS_AWORDS (128*GS_STRIDE)          // 4608 words per matrix
#define GS_STAGEW (2*GS_AWORDS)            // A + B per stage
#define GS_BYTES  (2*GS_STAGEW*4)          // 73728 bytes

template<int EPI>   // 0=none, 1=gelu(exact), 2=elu
__global__ void __launch_bounds__(256, 2) gemm_tc(const float* __restrict__ A,
                                                  const float* __restrict__ W,
                                                  const float* __restrict__ bias,
                                                  float* __restrict__ C,
                                                  int M, int N, int K)
{
    extern __shared__ uint32_t sm[];
    int tid  = threadIdx.x;
    int wid  = tid >> 5, lane = tid & 31;
    int wm   = wid >> 2;          // 0..1  (64 rows each)
    int wn   = wid & 3;           // 0..3  (32 cols each)
    int bm = blockIdx.y * 128, bn = blockIdx.x * 128;

    int r4 = lane >> 2;           // 0..7
    int c4 = lane & 3;            // 0..3

    float acc[4][4][4];
    #pragma unroll
    for (int mt = 0; mt < 4; mt++)
        #pragma unroll
        for (int nt = 0; nt < 4; nt++)
            #pragma unroll
            for (int u = 0; u < 4; u++) acc[mt][nt][u] = 0.0f;

    const float* Ab = A + (size_t)bm * K;
    const float* Wb = W + (size_t)bn * K;

    int T = K >> 5;
    for (int k0 = 0; k0 < T; k0++) {
        uint32_t* sA = sm + (k0 & 1) * GS_STAGEW;
        uint32_t* sB = sA + GS_AWORDS;
        // ---- gmem -> (cvt tf32) -> smem ----
        #pragma unroll
        for (int i = 0; i < 4; i++) {
            int lin = tid + i * 256;          // 0..1023
            int row = lin >> 3;               // 0..127
            int col = (lin & 7) << 2;         // 0..28
            float4 va = *(const float4*)(Ab + (size_t)row * K + k0 * 32 + col);
            float4 vb = *(const float4*)(Wb + (size_t)row * K + k0 * 32 + col);
            uint32_t* pa = sA + row * GS_STRIDE + col;
            uint32_t* pb = sB + row * GS_STRIDE + col;
            pa[0] = f2tf32(va.x); pa[1] = f2tf32(va.y);
            pa[2] = f2tf32(va.z); pa[3] = f2tf32(va.w);
            pb[0] = f2tf32(vb.x); pb[1] = f2tf32(vb.y);
            pb[2] = f2tf32(vb.z); pb[3] = f2tf32(vb.w);
        }
        __syncthreads();
        // ---- compute 4 k8 steps ----
        #pragma unroll
        for (int ks = 0; ks < 4; ks++) {
            uint32_t af[4][4];
            #pragma unroll
            for (int mt = 0; mt < 4; mt++) {
                const uint32_t* base = sA + (wm * 64 + mt * 16 + r4) * GS_STRIDE + ks * 8 + c4;
                af[mt][0] = base[0];
                af[mt][1] = base[8 * GS_STRIDE];
                af[mt][2] = base[4];
                af[mt][3] = base[8 * GS_STRIDE + 4];
            }
            uint32_t bf[4][2];
            #pragma unroll
            for (int nt = 0; nt < 4; nt++) {
                const uint32_t* base = sB + (wn * 32 + nt * 8 + r4) * GS_STRIDE + ks * 8 + c4;
                bf[nt][0] = base[0];
                bf[nt][1] = base[4];
            }
            #pragma unroll
            for (int mt = 0; mt < 4; mt++)
                #pragma unroll
                for (int nt = 0; nt < 4; nt++)
                    mma_tf32(acc[mt][nt][0], acc[mt][nt][1], acc[mt][nt][2], acc[mt][nt][3],
                             af[mt][0], af[mt][1], af[mt][2], af[mt][3],
                             bf[nt][0], bf[nt][1]);
        }
        __syncthreads();
    }

    // ---- epilogue: bias + activation + store ----
    #pragma unroll
    for (int mt = 0; mt < 4; mt++) {
        int gr = bm + wm * 64 + mt * 16 + r4;
        #pragma unroll
        for (int nt = 0; nt < 4; nt++) {
            int gc = bn + wn * 32 + nt * 8 + c4 * 2;
            float b0 = bias[gc], b1 = bias[gc + 1];
            float v[4];
            v[0] = acc[mt][nt][0] + b0;
            v[1] = acc[mt][nt][1] + b1;
            v[2] = acc[mt][nt][2] + b0;
            v[3] = acc[mt][nt][3] + b1;
            #pragma unroll
            for (int u = 0; u < 4; u++) {
                if (EPI == 1) v[u] = 0.5f * v[u] * (1.0f + erff(v[u] * 0.7071067811865476f));
                else if (EPI == 2) v[u] = v[u] > 0.0f ? v[u] : expm1f(v[u]);
            }
            *(float2*)(C + (size_t)gr * N + gc)       = make_float2(v[0], v[1]);
            *(float2*)(C + (size_t)(gr + 8) * N + gc) = make_float2(v[2], v[3]);
        }
    }
}

// ---------------- relative position bias table ----------------
__global__ void pbias_kernel(const float* __restrict__ rel_embed, float* __restrict__ pb)
{
    int d = blockIdx.x * blockDim.x + threadIdx.x;
    if (d >= 2047) return;
    int rel = d - 1023;
    int bucket = (rel > 0) ? 160 : 0;
    int r = rel < 0 ? -rel : rel;
    int val;
    if (r < 80) {
        val = r;
    } else {
        float rf = (float)(r < 1 ? 1 : r);
        float t = logf(rf / 80.0f) / 2.3025851f * 80.0f;
        int large = 80 + (int)t;
        val = large < 159 ? large : 159;
    }
    bucket += val;
    #pragma unroll
    for (int h = 0; h < NHH; h++)
        pb[h * 2048 + d] = rel_embed[bucket * NHH + h];
}

// ---------------- gate kernel ----------------
__global__ void gate_kernel(const float* __restrict__ x, const float* __restrict__ Wg,
                            const float* __restrict__ bg, const float* __restrict__ gc,
                            float* __restrict__ gate)
{
    __shared__ float xs[HH];
    int bs = blockIdx.x;
    int t = threadIdx.x;
    for (int i = t; i < HH; i += 128) xs[i] = x[(size_t)bs * HH + i];
    __syncthreads();
    int h = t >> 3, e = t & 7;
    float acc = bg[e];
    const float* wrow = Wg + e * HDD;
    const float* xrow = xs + h * HDD;
    #pragma unroll 8
    for (int d = 0; d < HDD; d++) acc += xrow[d] * wrow[d];
    acc += __shfl_xor_sync(0xffffffffu, acc, 1);
    acc += __shfl_xor_sync(0xffffffffu, acc, 2);
    float other = __shfl_xor_sync(0xffffffffu, acc, 4);
    if (e == 0) {
        float p0 = acc, p1 = other;
        float ga = 1.0f / (1.0f + expf(-p0));
        float gb = 1.0f / (1.0f + expf(-p1));
        float go = ga * (gb * gc[h] - 1.0f) + 2.0f;
        int b = bs >> 10, s = bs & 1023;
        gate[(b * NHH + h) * SS + s] = go;
    }
}

// ---------------- flash attention, 64x64 tiles, fp32 ----------------
__global__ void attn_kernel(const float* __restrict__ q, const float* __restrict__ k,
                            const float* __restrict__ v, const float* __restrict__ gate,
                            const float* __restrict__ pb, float* __restrict__ ctx)
{
    __shared__ float Qs [64][64];
    __shared__ float KPs[64][64];
    __shared__ float Vs [64][64];
    int t  = threadIdx.x;
    int tx = t & 15, ty = t >> 4;
    int i0 = blockIdx.x * 64;
    int h  = blockIdx.y;
    int b  = blockIdx.z;

    for (int idx = t; idx < 64*16; idx += 256) {
        int r = idx >> 4, c4 = (idx & 15) << 2;
        *(float4*)&Qs[r][c4] =
            *(const float4*)(q + ((size_t)(b*SS + i0 + r)) * HH + h*HDD + c4);
    }

    float gate_i[4];
    #pragma unroll
    for (int ii = 0; ii < 4; ii++)
        gate_i[ii] = gate[(b*NHH + h) * SS + i0 + ty*4 + ii];

    float m_run[4], l_run[4], acc[4][4];
    #pragma unroll
    for (int ii = 0; ii < 4; ii++) {
        m_run[ii] = -INFINITY; l_run[ii] = 0.0f;
        #pragma unroll
        for (int c = 0; c < 4; c++) acc[ii][c] = 0.0f;
    }

    const float* pbh = pb + h * 2048;

    for (int j0 = 0; j0 < SS; j0 += 64) {
        __syncthreads();
        for (int idx = t; idx < 64*16; idx += 256) {
            int r = idx >> 4, c4 = (idx & 15) << 2;
            float4 kv = *(const float4*)(k + ((size_t)(b*SS + j0 + r)) * HH + h*HDD + c4);
            KPs[c4+0][r] = kv.x; KPs[c4+1][r] = kv.y; KPs[c4+2][r] = kv.z; KPs[c4+3][r] = kv.w;
            *(float4*)&Vs[r][c4] =
                *(const float4*)(v + ((size_t)(b*SS + j0 + r)) * HH + h*HDD + c4);
        }
        __syncthreads();

        float s[4][4];
        #pragma unroll
        for (int ii = 0; ii < 4; ii++)
            #pragma unroll
            for (int jj = 0; jj < 4; jj++) s[ii][jj] = 0.0f;
        #pragma unroll 8
        for (int kk = 0; kk < 64; kk++) {
            float4 k4 = *(float4*)&KPs[kk][tx*4];
            #pragma unroll
            for (int ii = 0; ii < 4; ii++) {
                float qv = Qs[ty*4 + ii][kk];
                s[ii][0] += qv * k4.x; s[ii][1] += qv * k4.y;
                s[ii][2] += qv * k4.z; s[ii][3] += qv * k4.w;
            }
        }
        #pragma unroll
        for (int ii = 0; ii < 4; ii++) {
            int ig = i0 + ty*4 + ii;
            #pragma unroll
            for (int jj = 0; jj < 4; jj++) {
                int jg = j0 + tx*4 + jj;
                s[ii][jj] = s[ii][jj] * 0.125f + gate_i[ii] * pbh[jg - ig + 1023];
            }
        }
        #pragma unroll
        for (int ii = 0; ii < 4; ii++) {
            float mt = fmaxf(fmaxf(s[ii][0], s[ii][1]), fmaxf(s[ii][2], s[ii][3]));
            #pragma unroll
            for (int off = 8; off >= 1; off >>= 1)
                mt = fmaxf(mt, __shfl_xor_sync(0xffffffffu, mt, off));
            float mn = fmaxf(m_run[ii], mt);
            float alpha = expf(m_run[ii] - mn);
            float ls = 0.0f;
            #pragma unroll
            for (int jj = 0; jj < 4; jj++) {
                float p = expf(s[ii][jj] - mn);
                s[ii][jj] = p; ls += p;
            }
            #pragma unroll
            for (int off = 8; off >= 1; off >>= 1)
                ls += __shfl_xor_sync(0xffffffffu, ls, off);
            l_run[ii] = l_run[ii] * alpha + ls;
            m_run[ii] = mn;
            #pragma unroll
            for (int c = 0; c < 4; c++) acc[ii][c] *= alpha;
        }
        __syncthreads();
        #pragma unroll
        for (int ii = 0; ii < 4; ii++)
            *(float4*)&KPs[ty*4 + ii][tx*4] = make_float4(s[ii][0], s[ii][1], s[ii][2], s[ii][3]);
        __syncthreads();
        #pragma unroll 8
        for (int jj = 0; jj < 64; jj++) {
            float4 v4 = *(float4*)&Vs[jj][tx*4];
            #pragma unroll
            for (int ii = 0; ii < 4; ii++) {
                float p = KPs[ty*4 + ii][jj];
                acc[ii][0] += p * v4.x; acc[ii][1] += p * v4.y;
                acc[ii][2] += p * v4.z; acc[ii][3] += p * v4.w;
            }
        }
    }

    #pragma unroll
    for (int ii = 0; ii < 4; ii++) {
        float inv = 1.0f / l_run[ii];
        float4 o = make_float4(acc[ii][0]*inv, acc[ii][1]*inv, acc[ii][2]*inv, acc[ii][3]*inv);
        *(float4*)(ctx + ((size_t)(b*SS + i0 + ty*4 + ii)) * HH + h*HDD + tx*4) = o;
    }
}

// ---------------- residual-add + LayerNorm ----------------
__global__ void ln_kernel(const float* __restrict__ A, const float* __restrict__ B,
                          const float* __restrict__ C,
                          const float* __restrict__ g, const float* __restrict__ bt,
                          float* __restrict__ out)
{
    __shared__ float sm[8];
    int row = blockIdx.x;
    int t = threadIdx.x;
    size_t base = (size_t)row * HH;
    float vals[4];
    #pragma unroll
    for (int u = 0; u < 4; u++) {
        int i = t + u*256;
        float v = A[base + i] + B[base + i];
        if (C) v += C[base + i];
        vals[u] = v;
    }
    float sum = vals[0] + vals[1] + vals[2] + vals[3];
    #pragma unroll
    for (int off = 16; off >= 1; off >>= 1) sum += __shfl_xor_sync(0xffffffffu, sum, off);
    if ((t & 31) == 0) sm[t >> 5] = sum;
    __syncthreads();
    float tot = 0.0f;
    #pragma unroll
    for (int w = 0; w < 8; w++) tot += sm[w];
    float mean = tot * (1.0f / HH);
    __syncthreads();
    float vs = 0.0f;
    #pragma unroll
    for (int u = 0; u < 4; u++) { float d = vals[u] - mean; vs += d * d; }
    #pragma unroll
    for (int off = 16; off >= 1; off >>= 1) vs += __shfl_xor_sync(0xffffffffu, vs, off);
    if ((t & 31) == 0) sm[t >> 5] = vs;
    __syncthreads();
    float vtot = 0.0f;
    #pragma unroll
    for (int w = 0; w < 8; w++) vtot += sm[w];
    float rstd = rsqrtf(vtot * (1.0f / HH) + EPSF);
    #pragma unroll
    for (int u = 0; u < 4; u++) {
        int i = t + u*256;
        out[base + i] = (vals[u] - mean) * rstd * g[i] + bt[i];
    }
}

// ---------------- launch ----------------
extern "C" void kernel_launch(void* const* d_in, const int* in_sizes, int n_in,
                              void* d_out, int out_size)
{
    const float* x   = (const float*)d_in[0];
    const float* Wq  = (const float*)d_in[1];
    const float* bq  = (const float*)d_in[2];
    const float* Wk  = (const float*)d_in[3];
    const float* bk  = (const float*)d_in[4];
    const float* Wv  = (const float*)d_in[5];
    const float* bv  = (const float*)d_in[6];
    const float* Wo  = (const float*)d_in[7];
    const float* bo  = (const float*)d_in[8];
    const float* Wg  = (const float*)d_in[9];
    const float* bg  = (const float*)d_in[10];
    const float* gru = (const float*)d_in[11];
    const float* rel = (const float*)d_in[12];
    const float* l1g = (const float*)d_in[13];
    const float* l1b = (const float*)d_in[14];
    const float* W1  = (const float*)d_in[15];
    const float* b1  = (const float*)d_in[16];
    const float* W2  = (const float*)d_in[17];
    const float* b2  = (const float*)d_in[18];
    const float* l2g = (const float*)d_in[19];
    const float* l2b = (const float*)d_in[20];
    const float* Wad = (const float*)d_in[21];
    const float* bad = (const float*)d_in[22];
    const float* Wau = (const float*)d_in[23];
    const float* bau = (const float*)d_in[24];
    float* out = (float*)d_out;

    float *pq, *pk, *pv, *pctx, *patt, *ph, *pff1, *pff2, *pad1, *pad2, *pgate, *ppb;
    cudaGetSymbolAddress((void**)&pq,   g_q);
    cudaGetSymbolAddress((void**)&pk,   g_k);
    cudaGetSymbolAddress((void**)&pv,   g_v);
    cudaGetSymbolAddress((void**)&pctx, g_ctx);
    cudaGetSymbolAddress((void**)&patt, g_att);
    cudaGetSymbolAddress((void**)&ph,   g_h);
    cudaGetSymbolAddress((void**)&pff1, g_ff1);
    cudaGetSymbolAddress((void**)&pff2, g_ff2);
    cudaGetSymbolAddress((void**)&pad1, g_ad1);
    cudaGetSymbolAddress((void**)&pad2, g_ad2);
    cudaGetSymbolAddress((void**)&pgate, g_gate);
    cudaGetSymbolAddress((void**)&ppb,  g_pb);

    cudaFuncSetAttribute(gemm_tc<0>, cudaFuncAttributeMaxDynamicSharedMemorySize, GS_BYTES);
    cudaFuncSetAttribute(gemm_tc<1>, cudaFuncAttributeMaxDynamicSharedMemorySize, GS_BYTES);
    cudaFuncSetAttribute(gemm_tc<2>, cudaFuncAttributeMaxDynamicSharedMemorySize, GS_BYTES);

    // 1) relative position bias table
    pbias_kernel<<<(2047 + 127) / 128, 128>>>(rel, ppb);
    // 2) gates
    gate_kernel<<<BB * SS, 128>>>(x, Wg, bg, gru, pgate);
    // 3) QKV projections (mma.sync tf32)
    gemm_tc<0><<<dim3(HH/128, MM/128), 256, GS_BYTES>>>(x, Wq, bq, pq, MM, HH, HH);
    gemm_tc<0><<<dim3(HH/128, MM/128), 256, GS_BYTES>>>(x, Wk, bk, pk, MM, HH, HH);
    gemm_tc<0><<<dim3(HH/128, MM/128), 256, GS_BYTES>>>(x, Wv, bv, pv, MM, HH, HH);
    // 4) attention
    attn_kernel<<<dim3(SS/64, NHH, BB), 256>>>(pq, pk, pv, pgate, ppb, pctx);
    // 5) output projection
    gemm_tc<0><<<dim3(HH/128, MM/128), 256, GS_BYTES>>>(pctx, Wo, bo, patt, MM, HH, HH);
    // 6) residual + LN1
    ln_kernel<<<MM, 256>>>(x, patt, nullptr, l1g, l1b, ph);
    // 7) FFN
    gemm_tc<1><<<dim3(FFF/128, MM/128), 256, GS_BYTES>>>(ph, W1, b1, pff1, MM, FFF, HH);
    gemm_tc<0><<<dim3(HH/128, MM/128), 256, GS_BYTES>>>(pff1, W2, b2, pff2, MM, HH, FFF);
    // 8) adapter
    gemm_tc<2><<<dim3(ADD/128, MM/128), 256, GS_BYTES>>>(ph, Wad, bad, pad1, MM, ADD, HH);
    gemm_tc<0><<<dim3(HH/128, MM/128), 256, GS_BYTES>>>(pad1, Wau, bau, pad2, MM, HH, ADD);
    // 9) h + ff + adapt, LN2 -> out
    ln_kernel<<<MM, 256>>>(ph, pff2, pad2, l2g, l2b, out);
}

// round 4
// speedup vs baseline: 3.6236x; 1.5809x over previous
#include <cuda_runtime.h>
#include <math.h>
#include <stdint.h>

// ---------------- problem constants ----------------
#define BB   4
#define SS   1024
#define HH   1024
#define NHH  16
#define HDD  64
#define FFF  4096
#define ADD  256
#define MM   (BB*SS)          // 4096 rows
#define EPSF 1e-5f

// ---------------- scratch ----------------
__device__ float g_q  [MM*HH];
__device__ float g_k  [MM*HH];
__device__ float g_v  [MM*HH];
__device__ float g_ctx[MM*HH];
__device__ float g_att[MM*HH];
__device__ float g_h  [MM*HH];
__device__ float g_hr [MM*HH];
__device__ float g_ff1[(size_t)MM*FFF];
__device__ float g_ff2[MM*HH];
__device__ float g_ad1[MM*ADD];
__device__ float g_ad2[MM*HH];
__device__ float g_gate[BB*NHH*SS];
__device__ float g_pb  [NHH*2048];
// tf32-rounded operand copies
__device__ float g_xr [MM*HH];
__device__ float g_wq [HH*HH];
__device__ float g_wk [HH*HH];
__device__ float g_wv [HH*HH];
__device__ float g_wo [HH*HH];
__device__ float g_w1 [(size_t)FFF*HH];
__device__ float g_w2 [(size_t)HH*FFF];
__device__ float g_wad[ADD*HH];
__device__ float g_wau[HH*ADD];

// ---------------- helpers ----------------
__device__ __forceinline__ uint32_t f2tf32(float x) {
    uint32_t u;
    asm("cvt.rna.tf32.f32 %0, %1;" : "=r"(u) : "f"(x));
    return u;
}
__device__ __forceinline__ uint32_t smem_u32(const void* p) {
    uint32_t a;
    asm("{ .reg .u64 t; cvta.to.shared.u64 t, %1; cvt.u32.u64 %0, t; }" : "=r"(a) : "l"(p));
    return a;
}
__device__ __forceinline__ void cp16(uint32_t s, const void* g) {
    asm volatile("cp.async.cg.shared.global [%0], [%1], 16;" :: "r"(s), "l"(g));
}
#define CP_COMMIT() asm volatile("cp.async.commit_group;")
#define CP_WAIT(N)  asm volatile("cp.async.wait_group %0;" :: "n"(N))

__device__ __forceinline__ void mma_tf32(float& c0, float& c1, float& c2, float& c3,
                                         uint32_t a0, uint32_t a1, uint32_t a2, uint32_t a3,
                                         uint32_t b0, uint32_t b1) {
    asm volatile(
        "mma.sync.aligned.m16n8k8.row.col.f32.tf32.tf32.f32 "
        "{%0,%1,%2,%3}, {%4,%5,%6,%7}, {%8,%9}, {%0,%1,%2,%3};\n"
        : "+f"(c0), "+f"(c1), "+f"(c2), "+f"(c3)
        : "r"(a0), "r"(a1), "r"(a2), "r"(a3), "r"(b0), "r"(b1));
}

// ---------------- elementwise tf32 round ----------------
__global__ void round_tf32(const float* __restrict__ in, uint32_t* __restrict__ out, int n)
{
    int i = (blockIdx.x * 256 + threadIdx.x) * 4;
    if (i >= n) return;
    float4 t = *(const float4*)(in + i);
    uint4 o;
    o.x = f2tf32(t.x); o.y = f2tf32(t.y); o.z = f2tf32(t.z); o.w = f2tf32(t.w);
    *(uint4*)(out + i) = o;
}

// ================= mma.sync tf32 GEMM (cp.async pipelined) =================
// Inputs A and W must already be tf32-rounded bit patterns.
// C[M,N] = A[M,K] @ W[N,K]^T + bias, epilogue.
#define GS_STRIDE 36
#define GS_AWORDS (128*GS_STRIDE)
#define GS_STAGEW (2*GS_AWORDS)
#define GS_BYTES  (2*GS_STAGEW*4)   // 73728

template<int EPI, int RND>   // EPI: 0=none,1=gelu,2=elu ; RND: round output to tf32
__global__ void __launch_bounds__(256, 2) gemm_tc(const float* __restrict__ A,
                                                  const float* __restrict__ W,
                                                  const float* __restrict__ bias,
                                                  float* __restrict__ C,
                                                  int M, int N, int K)
{
    extern __shared__ uint32_t sm[];
    int tid  = threadIdx.x;
    int wid  = tid >> 5, lane = tid & 31;
    int wm   = wid >> 2;          // 0..1
    int wn   = wid & 3;           // 0..3
    int bm = blockIdx.y * 128, bn = blockIdx.x * 128;
    int r4 = lane >> 2;
    int c4 = lane & 3;

    float acc[4][4][4];
    #pragma unroll
    for (int mt = 0; mt < 4; mt++)
        #pragma unroll
        for (int nt = 0; nt < 4; nt++)
            #pragma unroll
            for (int u = 0; u < 4; u++) acc[mt][nt][u] = 0.0f;

    const float* Ab = A + (size_t)bm * K;
    const float* Wb = W + (size_t)bn * K;

    int lrow = tid >> 3;            // 0..31
    int lcol = (tid & 7) << 2;      // 0,4,..28
    const float* aptr = Ab + (size_t)lrow * K + lcol;
    const float* wptr = Wb + (size_t)lrow * K + lcol;
    uint32_t sb = smem_u32(sm);
    uint32_t sa_base = sb + (uint32_t)(lrow * GS_STRIDE + lcol) * 4;

    int T = K >> 5;

    // prologue: tile 0 -> buf 0
    #pragma unroll
    for (int i = 0; i < 4; i++) {
        cp16(sa_base + (uint32_t)(i * 32 * GS_STRIDE) * 4, aptr + (size_t)(i * 32) * K);
        cp16(sa_base + (uint32_t)(GS_AWORDS + i * 32 * GS_STRIDE) * 4, wptr + (size_t)(i * 32) * K);
    }
    CP_COMMIT();

    for (int k0 = 0; k0 < T; k0++) {
        int buf = k0 & 1;
        if (k0 + 1 < T) {
            int nb = buf ^ 1;
            const float* ap = aptr + (k0 + 1) * 32;
            const float* wp = wptr + (k0 + 1) * 32;
            uint32_t so = sa_base + (uint32_t)(nb * GS_STAGEW) * 4;
            #pragma unroll
            for (int i = 0; i < 4; i++) {
                cp16(so + (uint32_t)(i * 32 * GS_STRIDE) * 4, ap + (size_t)(i * 32) * K);
                cp16(so + (uint32_t)(GS_AWORDS + i * 32 * GS_STRIDE) * 4, wp + (size_t)(i * 32) * K);
            }
            CP_COMMIT();
            CP_WAIT(1);
        } else {
            CP_WAIT(0);
        }
        __syncthreads();

        const uint32_t* sA = sm + buf * GS_STAGEW;
        const uint32_t* sB = sA + GS_AWORDS;
        #pragma unroll
        for (int ks = 0; ks < 4; ks++) {
            uint32_t af[4][4];
            #pragma unroll
            for (int mt = 0; mt < 4; mt++) {
                const uint32_t* p = sA + (wm * 64 + mt * 16 + r4) * GS_STRIDE + ks * 8 + c4;
                af[mt][0] = p[0];
                af[mt][1] = p[8 * GS_STRIDE];
                af[mt][2] = p[4];
                af[mt][3] = p[8 * GS_STRIDE + 4];
            }
            uint32_t bf[4][2];
            #pragma unroll
            for (int nt = 0; nt < 4; nt++) {
                const uint32_t* p = sB + (wn * 32 + nt * 8 + r4) * GS_STRIDE + ks * 8 + c4;
                bf[nt][0] = p[0];
                bf[nt][1] = p[4];
            }
            #pragma unroll
            for (int mt = 0; mt < 4; mt++)
                #pragma unroll
                for (int nt = 0; nt < 4; nt++)
                    mma_tf32(acc[mt][nt][0], acc[mt][nt][1], acc[mt][nt][2], acc[mt][nt][3],
                             af[mt][0], af[mt][1], af[mt][2], af[mt][3],
                             bf[nt][0], bf[nt][1]);
        }
        __syncthreads();
    }

    // ---- epilogue ----
    #pragma unroll
    for (int mt = 0; mt < 4; mt++) {
        int gr = bm + wm * 64 + mt * 16 + r4;
        #pragma unroll
        for (int nt = 0; nt < 4; nt++) {
            int gc = bn + wn * 32 + nt * 8 + c4 * 2;
            float b0 = bias[gc], b1 = bias[gc + 1];
            float v[4];
            v[0] = acc[mt][nt][0] + b0;
            v[1] = acc[mt][nt][1] + b1;
            v[2] = acc[mt][nt][2] + b0;
            v[3] = acc[mt][nt][3] + b1;
            #pragma unroll
            for (int u = 0; u < 4; u++) {
                if (EPI == 1) v[u] = 0.5f * v[u] * (1.0f + erff(v[u] * 0.7071067811865476f));
                else if (EPI == 2) v[u] = v[u] > 0.0f ? v[u] : expm1f(v[u]);
                if (RND) v[u] = __uint_as_float(f2tf32(v[u]));
            }
            *(float2*)(C + (size_t)gr * N + gc)       = make_float2(v[0], v[1]);
            *(float2*)(C + (size_t)(gr + 8) * N + gc) = make_float2(v[2], v[3]);
        }
    }
}

// ---------------- relative position bias table ----------------
__global__ void pbias_kernel(const float* __restrict__ rel_embed, float* __restrict__ pb)
{
    int d = blockIdx.x * blockDim.x + threadIdx.x;
    if (d >= 2047) return;
    int rel = d - 1023;
    int bucket = (rel > 0) ? 160 : 0;
    int r = rel < 0 ? -rel : rel;
    int val;
    if (r < 80) {
        val = r;
    } else {
        float rf = (float)(r < 1 ? 1 : r);
        float t = logf(rf / 80.0f) / 2.3025851f * 80.0f;
        int large = 80 + (int)t;
        val = large < 159 ? large : 159;
    }
    bucket += val;
    #pragma unroll
    for (int h = 0; h < NHH; h++)
        pb[h * 2048 + d] = rel_embed[bucket * NHH + h];
}

// ---------------- gate kernel ----------------
__global__ void gate_kernel(const float* __restrict__ x, const float* __restrict__ Wg,
                            const float* __restrict__ bg, const float* __restrict__ gc,
                            float* __restrict__ gate)
{
    __shared__ float xs[HH];
    int bs = blockIdx.x;
    int t = threadIdx.x;
    for (int i = t; i < HH; i += 128) xs[i] = x[(size_t)bs * HH + i];
    __syncthreads();
    int h = t >> 3, e = t & 7;
    float acc = bg[e];
    const float* wrow = Wg + e * HDD;
    const float* xrow = xs + h * HDD;
    #pragma unroll 8
    for (int d = 0; d < HDD; d++) acc += xrow[d] * wrow[d];
    acc += __shfl_xor_sync(0xffffffffu, acc, 1);
    acc += __shfl_xor_sync(0xffffffffu, acc, 2);
    float other = __shfl_xor_sync(0xffffffffu, acc, 4);
    if (e == 0) {
        float p0 = acc, p1 = other;
        float ga = 1.0f / (1.0f + expf(-p0));
        float gb = 1.0f / (1.0f + expf(-p1));
        float go = ga * (gb * gc[h] - 1.0f) + 2.0f;
        int b = bs >> 10, s = bs & 1023;
        gate[(b * NHH + h) * SS + s] = go;
    }
}

// ================= tensor-core flash attention =================
// q,k,v hold tf32-rounded bit patterns. ctx written tf32-rounded.
// Grid (S/64, NH, B), 128 threads = 4 warps; each warp owns 16 Q rows.
#define AQS 68
#define AVS 72
#define ASM_WORDS (3*64*AQS + 64*AVS)        // Qs, Ks, Ps, Vs
#define ASM_BYTES (ASM_WORDS*4)              // 70656

__global__ void __launch_bounds__(128, 3) attn_tc(const float* __restrict__ q,
                                                  const float* __restrict__ k,
                                                  const float* __restrict__ v,
                                                  const float* __restrict__ gate,
                                                  const float* __restrict__ pb,
                                                  float* __restrict__ ctx)
{
    extern __shared__ uint32_t as_[];
    uint32_t* Qs = as_;
    uint32_t* Ks = Qs + 64 * AQS;
    uint32_t* Ps = Ks + 64 * AQS;
    uint32_t* Vs = Ps + 64 * AQS;

    int tid = threadIdx.x, wid = tid >> 5, lane = tid & 31;
    int r4 = lane >> 2, c4 = lane & 3;
    int i0 = blockIdx.x * 64, h = blockIdx.y, b = blockIdx.z;

    const uint32_t* qb = (const uint32_t*)q + ((size_t)(b * SS + i0)) * HH + h * HDD;
    const uint32_t* kb = (const uint32_t*)k + ((size_t)(b * SS)) * HH + h * HDD;
    const uint32_t* vb = (const uint32_t*)v + ((size_t)(b * SS)) * HH + h * HDD;

    // ---- load Q tile ----
    for (int idx = tid; idx < 64 * 16; idx += 128) {
        int r = idx >> 4, c = (idx & 15) << 2;
        *(uint4*)(Qs + r * AQS + c) = *(const uint4*)(qb + (size_t)r * HH + c);
    }
    __syncthreads();

    // ---- Q fragments (kept in registers for the whole kernel) ----
    uint32_t qf[8][4];
    {
        const uint32_t* qp = Qs + (wid * 16 + r4) * AQS + c4;
        #pragma unroll
        for (int ks = 0; ks < 8; ks++) {
            qf[ks][0] = qp[ks * 8];
            qf[ks][1] = qp[8 * AQS + ks * 8];
            qf[ks][2] = qp[ks * 8 + 4];
            qf[ks][3] = qp[8 * AQS + ks * 8 + 4];
        }
    }

    float gate0 = gate[(b * NHH + h) * SS + i0 + wid * 16 + r4];
    float gate1 = gate[(b * NHH + h) * SS + i0 + wid * 16 + r4 + 8];
    const float* pbh = pb + h * 2048 + 1023 - (i0 + wid * 16 + r4);

    float m0 = -INFINITY, m1 = -INFINITY, l0 = 0.0f, l1 = 0.0f;
    float oa[8][4];
    #pragma unroll
    for (int nt = 0; nt < 8; nt++)
        #pragma unroll
        for (int u = 0; u < 4; u++) oa[nt][u] = 0.0f;

    uint32_t ksm = smem_u32(Ks);
    uint32_t vsm = smem_u32(Vs);

    for (int j0 = 0; j0 < SS; j0 += 64) {
        __syncthreads();   // Ks/Vs free to overwrite (also orders Ps)
        for (int idx = tid; idx < 64 * 16; idx += 128) {
            int r = idx >> 4, c = (idx & 15) << 2;
            cp16(ksm + (uint32_t)(r * AQS + c) * 4, kb + (size_t)(j0 + r) * HH + c);
            cp16(vsm + (uint32_t)(r * AVS + c) * 4, vb + (size_t)(j0 + r) * HH + c);
        }
        CP_COMMIT();
        CP_WAIT(0);
        __syncthreads();

        // ---- S = Q K^T ----
        float sf[8][4];
        #pragma unroll
        for (int nt = 0; nt < 8; nt++)
            #pragma unroll
            for (int u = 0; u < 4; u++) sf[nt][u] = 0.0f;
        #pragma unroll
        for (int ks = 0; ks < 8; ks++) {
            #pragma unroll
            for (int nt = 0; nt < 8; nt++) {
                const uint32_t* p = Ks + (nt * 8 + r4) * AQS + ks * 8 + c4;
                mma_tf32(sf[nt][0], sf[nt][1], sf[nt][2], sf[nt][3],
                         qf[ks][0], qf[ks][1], qf[ks][2], qf[ks][3],
                         p[0], p[4]);
            }
        }

        // ---- scale + gated relative bias ----
        #pragma unroll
        for (int nt = 0; nt < 8; nt++) {
            int j = j0 + nt * 8 + 2 * c4;
            float pb0 = pbh[j];
            float pb1 = pbh[j + 1];
            float pb2 = pbh[j - 8];
            float pb3 = pbh[j - 7];
            sf[nt][0] = sf[nt][0] * 0.125f + gate0 * pb0;
            sf[nt][1] = sf[nt][1] * 0.125f + gate0 * pb1;
            sf[nt][2] = sf[nt][2] * 0.125f + gate1 * pb2;
            sf[nt][3] = sf[nt][3] * 0.125f + gate1 * pb3;
        }

        // ---- online softmax ----
        float mx0 = -INFINITY, mx1 = -INFINITY;
        #pragma unroll
        for (int nt = 0; nt < 8; nt++) {
            mx0 = fmaxf(mx0, fmaxf(sf[nt][0], sf[nt][1]));
            mx1 = fmaxf(mx1, fmaxf(sf[nt][2], sf[nt][3]));
        }
        mx0 = fmaxf(mx0, __shfl_xor_sync(0xffffffffu, mx0, 1));
        mx0 = fmaxf(mx0, __shfl_xor_sync(0xffffffffu, mx0, 2));
        mx1 = fmaxf(mx1, __shfl_xor_sync(0xffffffffu, mx1, 1));
        mx1 = fmaxf(mx1, __shfl_xor_sync(0xffffffffu, mx1, 2));
        float mn0 = fmaxf(m0, mx0), mn1 = fmaxf(m1, mx1);
        float a0 = __expf(m0 - mn0), a1 = __expf(m1 - mn1);

        float ls0 = 0.0f, ls1 = 0.0f;
        uint32_t* pr0 = Ps + (wid * 16 + r4) * AQS + 2 * c4;
        uint32_t* pr1 = pr0 + 8 * AQS;
        #pragma unroll
        for (int nt = 0; nt < 8; nt++) {
            float p0 = __expf(sf[nt][0] - mn0);
            float p1 = __expf(sf[nt][1] - mn0);
            float p2 = __expf(sf[nt][2] - mn1);
            float p3 = __expf(sf[nt][3] - mn1);
            ls0 += p0 + p1; ls1 += p2 + p3;
            pr0[nt * 8]     = f2tf32(p0);
            pr0[nt * 8 + 1] = f2tf32(p1);
            pr1[nt * 8]     = f2tf32(p2);
            pr1[nt * 8 + 1] = f2tf32(p3);
        }
        ls0 += __shfl_xor_sync(0xffffffffu, ls0, 1);
        ls0 += __shfl_xor_sync(0xffffffffu, ls0, 2);
        ls1 += __shfl_xor_sync(0xffffffffu, ls1, 1);
        ls1 += __shfl_xor_sync(0xffffffffu, ls1, 2);
        l0 = l0 * a0 + ls0;  l1 = l1 * a1 + ls1;
        m0 = mn0;  m1 = mn1;
        #pragma unroll
        for (int nt = 0; nt < 8; nt++) {
            oa[nt][0] *= a0; oa[nt][1] *= a0;
            oa[nt][2] *= a1; oa[nt][3] *= a1;
        }
        __syncwarp();

        // ---- O += P V ----
        const uint32_t* pp = Ps + (wid * 16 + r4) * AQS + c4;
        #pragma unroll
        for (int ks = 0; ks < 8; ks++) {
            uint32_t af0 = pp[ks * 8];
            uint32_t af1 = pp[8 * AQS + ks * 8];
            uint32_t af2 = pp[ks * 8 + 4];
            uint32_t af3 = pp[8 * AQS + ks * 8 + 4];
            #pragma unroll
            for (int nt = 0; nt < 8; nt++) {
                uint32_t b0 = Vs[(ks * 8 + c4) * AVS + nt * 8 + r4];
                uint32_t b1 = Vs[(ks * 8 + c4 + 4) * AVS + nt * 8 + r4];
                mma_tf32(oa[nt][0], oa[nt][1], oa[nt][2], oa[nt][3],
                         af0, af1, af2, af3, b0, b1);
            }
        }
    }

    // ---- epilogue: normalize, round to tf32, store ----
    float inv0 = 1.0f / l0, inv1 = 1.0f / l1;
    uint32_t* cb0 = (uint32_t*)ctx + ((size_t)(b * SS + i0 + wid * 16 + r4)) * HH + h * HDD;
    uint32_t* cb1 = cb0 + 8 * HH;
    #pragma unroll
    for (int nt = 0; nt < 8; nt++) {
        uint2 w0, w1;
        w0.x = f2tf32(oa[nt][0] * inv0);
        w0.y = f2tf32(oa[nt][1] * inv0);
        w1.x = f2tf32(oa[nt][2] * inv1);
        w1.y = f2tf32(oa[nt][3] * inv1);
        *(uint2*)(cb0 + nt * 8 + 2 * c4) = w0;
        *(uint2*)(cb1 + nt * 8 + 2 * c4) = w1;
    }
}

// ---------------- residual-add + LayerNorm (+ optional tf32 copy) ----------------
__global__ void ln_kernel(const float* __restrict__ A, const float* __restrict__ B,
                          const float* __restrict__ C,
                          const float* __restrict__ g, const float* __restrict__ bt,
                          float* __restrict__ out, float* __restrict__ out2)
{
    __shared__ float sm[8];
    int row = blockIdx.x;
    int t = threadIdx.x;
    size_t base = (size_t)row * HH;
    float vals[4];
    #pragma unroll
    for (int u = 0; u < 4; u++) {
        int i = t + u*256;
        float v = A[base + i] + B[base + i];
        if (C) v += C[base + i];
        vals[u] = v;
    }
    float sum = vals[0] + vals[1] + vals[2] + vals[3];
    #pragma unroll
    for (int off = 16; off >= 1; off >>= 1) sum += __shfl_xor_sync(0xffffffffu, sum, off);
    if ((t & 31) == 0) sm[t >> 5] = sum;
    __syncthreads();
    float tot = 0.0f;
    #pragma unroll
    for (int w = 0; w < 8; w++) tot += sm[w];
    float mean = tot * (1.0f / HH);
    __syncthreads();
    float vs = 0.0f;
    #pragma unroll
    for (int u = 0; u < 4; u++) { float d = vals[u] - mean; vs += d * d; }
    #pragma unroll
    for (int off = 16; off >= 1; off >>= 1) vs += __shfl_xor_sync(0xffffffffu, vs, off);
    if ((t & 31) == 0) sm[t >> 5] = vs;
    __syncthreads();
    float vtot = 0.0f;
    #pragma unroll
    for (int w = 0; w < 8; w++) vtot += sm[w];
    float rstd = rsqrtf(vtot * (1.0f / HH) + EPSF);
    #pragma unroll
    for (int u = 0; u < 4; u++) {
        int i = t + u*256;
        float r = (vals[u] - mean) * rstd * g[i] + bt[i];
        out[base + i] = r;
        if (out2) out2[base + i] = __uint_as_float(f2tf32(r));
    }
}

// ---------------- launch ----------------
extern "C" void kernel_launch(void* const* d_in, const int* in_sizes, int n_in,
                              void* d_out, int out_size)
{
    const float* x   = (const float*)d_in[0];
    const float* Wq  = (const float*)d_in[1];
    const float* bq  = (const float*)d_in[2];
    const float* Wk  = (const float*)d_in[3];
    const float* bk  = (const float*)d_in[4];
    const float* Wv  = (const float*)d_in[5];
    const float* bv  = (const float*)d_in[6];
    const float* Wo  = (const float*)d_in[7];
    const float* bo  = (const float*)d_in[8];
    const float* Wg  = (const float*)d_in[9];
    const float* bg  = (const float*)d_in[10];
    const float* gru = (const float*)d_in[11];
    const float* rel = (const float*)d_in[12];
    const float* l1g = (const float*)d_in[13];
    const float* l1b = (const float*)d_in[14];
    const float* W1  = (const float*)d_in[15];
    const float* b1  = (const float*)d_in[16];
    const float* W2  = (const float*)d_in[17];
    const float* b2  = (const float*)d_in[18];
    const float* l2g = (const float*)d_in[19];
    const float* l2b = (const float*)d_in[20];
    const float* Wad = (const float*)d_in[21];
    const float* bad = (const float*)d_in[22];
    const float* Wau = (const float*)d_in[23];
    const float* bau = (const float*)d_in[24];
    float* out = (float*)d_out;

    float *pq, *pk, *pv, *pctx, *patt, *ph, *phr, *pff1, *pff2, *pad1, *pad2, *pgate, *ppb;
    float *pxr, *pwq, *pwk, *pwv, *pwo, *pw1, *pw2, *pwad, *pwau;
    cudaGetSymbolAddress((void**)&pq,   g_q);
    cudaGetSymbolAddress((void**)&pk,   g_k);
    cudaGetSymbolAddress((void**)&pv,   g_v);
    cudaGetSymbolAddress((void**)&pctx, g_ctx);
    cudaGetSymbolAddress((void**)&patt, g_att);
    cudaGetSymbolAddress((void**)&ph,   g_h);
    cudaGetSymbolAddress((void**)&phr,  g_hr);
    cudaGetSymbolAddress((void**)&pff1, g_ff1);
    cudaGetSymbolAddress((void**)&pff2, g_ff2);
    cudaGetSymbolAddress((void**)&pad1, g_ad1);
    cudaGetSymbolAddress((void**)&pad2, g_ad2);
    cudaGetSymbolAddress((void**)&pgate, g_gate);
    cudaGetSymbolAddress((void**)&ppb,  g_pb);
    cudaGetSymbolAddress((void**)&pxr,  g_xr);
    cudaGetSymbolAddress((void**)&pwq,  g_wq);
    cudaGetSymbolAddress((void**)&pwk,  g_wk);
    cudaGetSymbolAddress((void**)&pwv,  g_wv);
    cudaGetSymbolAddress((void**)&pwo,  g_wo);
    cudaGetSymbolAddress((void**)&pw1,  g_w1);
    cudaGetSymbolAddress((void**)&pw2,  g_w2);
    cudaGetSymbolAddress((void**)&pwad, g_wad);
    cudaGetSymbolAddress((void**)&pwau, g_wau);

    cudaFuncSetAttribute(gemm_tc<0,0>, cudaFuncAttributeMaxDynamicSharedMemorySize, GS_BYTES);
    cudaFuncSetAttribute(gemm_tc<0,1>, cudaFuncAttributeMaxDynamicSharedMemorySize, GS_BYTES);
    cudaFuncSetAttribute(gemm_tc<1,1>, cudaFuncAttributeMaxDynamicSharedMemorySize, GS_BYTES);
    cudaFuncSetAttribute(gemm_tc<2,1>, cudaFuncAttributeMaxDynamicSharedMemorySize, GS_BYTES);
    cudaFuncSetAttribute(attn_tc, cudaFuncAttributeMaxDynamicSharedMemorySize, ASM_BYTES);

    // 0) pre-round all GEMM operands to tf32
    round_tf32<<<(MM*HH)/1024, 256>>>(x,  (uint32_t*)pxr, MM*HH);
    round_tf32<<<(HH*HH)/1024, 256>>>(Wq, (uint32_t*)pwq, HH*HH);
    round_tf32<<<(HH*HH)/1024, 256>>>(Wk, (uint32_t*)pwk, HH*HH);
    round_tf32<<<(HH*HH)/1024, 256>>>(Wv, (uint32_t*)pwv, HH*HH);
    round_tf32<<<(HH*HH)/1024, 256>>>(Wo, (uint32_t*)pwo, HH*HH);
    round_tf32<<<(FFF*HH)/1024, 256>>>(W1, (uint32_t*)pw1, FFF*HH);
    round_tf32<<<(FFF*HH)/1024, 256>>>(W2, (uint32_t*)pw2, FFF*HH);
    round_tf32<<<(ADD*HH)/1024, 256>>>(Wad, (uint32_t*)pwad, ADD*HH);
    round_tf32<<<(ADD*HH)/1024, 256>>>(Wau, (uint32_t*)pwau, ADD*HH);

    // 1) relative position bias table
    pbias_kernel<<<(2047 + 127) / 128, 128>>>(rel, ppb);
    // 2) gates
    gate_kernel<<<BB * SS, 128>>>(x, Wg, bg, gru, pgate);
    // 3) QKV projections (outputs tf32-rounded for attention)
    gemm_tc<0,1><<<dim3(HH/128, MM/128), 256, GS_BYTES>>>(pxr, pwq, bq, pq, MM, HH, HH);
    gemm_tc<0,1><<<dim3(HH/128, MM/128), 256, GS_BYTES>>>(pxr, pwk, bk, pk, MM, HH, HH);
    gemm_tc<0,1><<<dim3(HH/128, MM/128), 256, GS_BYTES>>>(pxr, pwv, bv, pv, MM, HH, HH);
    // 4) attention (tensor cores; ctx tf32-rounded)
    attn_tc<<<dim3(SS/64, NHH, BB), 128, ASM_BYTES>>>(pq, pk, pv, pgate, ppb, pctx);
    // 5) output projection
    gemm_tc<0,0><<<dim3(HH/128, MM/128), 256, GS_BYTES>>>(pctx, pwo, bo, patt, MM, HH, HH);
    // 6) residual + LN1 (h fp32 + tf32 copy)
    ln_kernel<<<MM, 256>>>(x, patt, nullptr, l1g, l1b, ph, phr);
    // 7) FFN
    gemm_tc<1,1><<<dim3(FFF/128, MM/128), 256, GS_BYTES>>>(phr, pw1, b1, pff1, MM, FFF, HH);
    gemm_tc<0,0><<<dim3(HH/128, MM/128), 256, GS_BYTES>>>(pff1, pw2, b2, pff2, MM, HH, FFF);
    // 8) adapter
    gemm_tc<2,1><<<dim3(ADD/128, MM/128), 256, GS_BYTES>>>(phr, pwad, bad, pad1, MM, ADD, HH);
    gemm_tc<0,0><<<dim3(HH/128, MM/128), 256, GS_BYTES>>>(pad1, pwau, bau, pad2, MM, HH, ADD);
    // 9) h + ff + adapt, LN2 -> out
    ln_kernel<<<MM, 256>>>(ph, pff2, pad2, l2g, l2b, out, nullptr);
}

// round 5
// speedup vs baseline: 3.6453x; 1.0060x over previous
#include <cuda_runtime.h>
#include <math.h>
#include <stdint.h>

// ---------------- problem constants ----------------
#define BB   4
#define SS   1024
#define HH   1024
#define NHH  16
#define HDD  64
#define FFF  4096
#define ADD  256
#define MM   (BB*SS)          // 4096 rows
#define EPSF 1e-5f
#define QKVN 3072
#define FAK  (FFF+ADD)        // 4352 fused K for ffn2+adapter

// ---------------- scratch ----------------
__device__ float g_qkv [(size_t)MM*QKVN];
__device__ float g_ctx [MM*HH];
__device__ float g_att [MM*HH];
__device__ float g_h   [MM*HH];
__device__ float g_hr  [MM*HH];
__device__ float g_ff1 [(size_t)MM*FAK];
__device__ float g_ff2 [MM*HH];
__device__ float g_gate[BB*NHH*SS];
__device__ float g_pb  [NHH*2048];
// tf32-rounded operand copies
__device__ float g_xr  [MM*HH];
__device__ float g_wqkv[QKVN*HH];
__device__ float g_wo  [HH*HH];
__device__ float g_w1  [(size_t)FFF*HH];
__device__ float g_w2c [(size_t)HH*FAK];
__device__ float g_wad [ADD*HH];
__device__ float g_bqkv[QKVN];
__device__ float g_b2c [HH];

// ---------------- helpers ----------------
__device__ __forceinline__ uint32_t f2tf32(float x) {
    uint32_t u;
    asm("cvt.rna.tf32.f32 %0, %1;" : "=r"(u) : "f"(x));
    return u;
}
__device__ __forceinline__ uint32_t smem_u32(const void* p) {
    uint32_t a;
    asm("{ .reg .u64 t; cvta.to.shared.u64 t, %1; cvt.u32.u64 %0, t; }" : "=r"(a) : "l"(p));
    return a;
}
__device__ __forceinline__ void cp16(uint32_t s, const void* g) {
    asm volatile("cp.async.cg.shared.global [%0], [%1], 16;" :: "r"(s), "l"(g));
}
#define CP_COMMIT() asm volatile("cp.async.commit_group;")
#define CP_WAIT(N)  asm volatile("cp.async.wait_group %0;" :: "n"(N))

__device__ __forceinline__ void mma_tf32(float& c0, float& c1, float& c2, float& c3,
                                         uint32_t a0, uint32_t a1, uint32_t a2, uint32_t a3,
                                         uint32_t b0, uint32_t b1) {
    asm volatile(
        "mma.sync.aligned.m16n8k8.row.col.f32.tf32.tf32.f32 "
        "{%0,%1,%2,%3}, {%4,%5,%6,%7}, {%8,%9}, {%0,%1,%2,%3};\n"
        : "+f"(c0), "+f"(c1), "+f"(c2), "+f"(c3)
        : "r"(a0), "r"(a1), "r"(a2), "r"(a3), "r"(b0), "r"(b1));
}

// ---------------- elementwise tf32 round (contiguous) ----------------
__global__ void round_tf32(const float* __restrict__ in, uint32_t* __restrict__ out, int n)
{
    int i = (blockIdx.x * 256 + threadIdx.x) * 4;
    if (i >= n) return;
    float4 t = *(const float4*)(in + i);
    uint4 o;
    o.x = f2tf32(t.x); o.y = f2tf32(t.y); o.z = f2tf32(t.z); o.w = f2tf32(t.w);
    *(uint4*)(out + i) = o;
}

// ---------------- strided tf32 round: out[row*ldo + col] ----------------
__global__ void round_tf32_pitch(const float* __restrict__ in, uint32_t* __restrict__ out,
                                 int rows, int cols, int ldo)
{
    int i = (blockIdx.x * 256 + threadIdx.x) * 4;
    if (i >= rows * cols) return;
    int row = i / cols, col = i - row * cols;
    float4 t = *(const float4*)(in + (size_t)row * cols + col);
    uint4 o;
    o.x = f2tf32(t.x); o.y = f2tf32(t.y); o.z = f2tf32(t.z); o.w = f2tf32(t.w);
    *(uint4*)(out + (size_t)row * ldo + col) = o;
}

__global__ void bias_sum(const float* __restrict__ a, const float* __restrict__ b,
                         float* __restrict__ o, int n)
{
    int i = blockIdx.x * 256 + threadIdx.x;
    if (i < n) o[i] = a[i] + b[i];
}

// ================= mma.sync tf32 GEMM (cp.async, single sync per tile) =================
// Inputs A and W must already be tf32-rounded. A pitch == K, W pitch == K.
// C[M rows, N cols] with row pitch ldc; C = A @ W^T + bias, epilogue.
#define GS_STRIDE 36
#define GS_AWORDS (128*GS_STRIDE)
#define GS_STAGEW (2*GS_AWORDS)
#define GS_BYTES  (2*GS_STAGEW*4)   // 73728

template<int EPI, int RND>   // EPI: 0=none,1=gelu,2=elu ; RND: round output to tf32
__global__ void __launch_bounds__(256, 2) gemm_tc(const float* __restrict__ A,
                                                  const float* __restrict__ W,
                                                  const float* __restrict__ bias,
                                                  float* __restrict__ C,
                                                  int M, int N, int K, int ldc)
{
    extern __shared__ uint32_t sm[];
    int tid  = threadIdx.x;
    int wid  = tid >> 5, lane = tid & 31;
    int wm   = wid >> 2;          // 0..1
    int wn   = wid & 3;           // 0..3
    int bm = blockIdx.y * 128, bn = blockIdx.x * 128;
    int r4 = lane >> 2;
    int c4 = lane & 3;

    float acc[4][4][4];
    #pragma unroll
    for (int mt = 0; mt < 4; mt++)
        #pragma unroll
        for (int nt = 0; nt < 4; nt++)
            #pragma unroll
            for (int u = 0; u < 4; u++) acc[mt][nt][u] = 0.0f;

    int lrow = tid >> 3;            // 0..31
    int lcol = (tid & 7) << 2;      // 0,4,..28
    const float* aptr = A + (size_t)(bm + lrow) * K + lcol;
    const float* wptr = W + (size_t)(bn + lrow) * K + lcol;
    uint32_t sb = smem_u32(sm);
    uint32_t sa_base = sb + (uint32_t)(lrow * GS_STRIDE + lcol) * 4;

    int T = K >> 5;

    // prologue: tile 0 -> buf 0
    #pragma unroll
    for (int i = 0; i < 4; i++) {
        cp16(sa_base + (uint32_t)(i * 32 * GS_STRIDE) * 4, aptr + (size_t)(i * 32) * K);
        cp16(sa_base + (uint32_t)(GS_AWORDS + i * 32 * GS_STRIDE) * 4, wptr + (size_t)(i * 32) * K);
    }
    CP_COMMIT();

    for (int k0 = 0; k0 < T; k0++) {
        int buf = k0 & 1;
        CP_WAIT(0);
        __syncthreads();   // tile k0 visible; all warps done computing buf^1
        if (k0 + 1 < T) {
            const float* ap = aptr + (k0 + 1) * 32;
            const float* wp = wptr + (k0 + 1) * 32;
            uint32_t so = sa_base + (uint32_t)((buf ^ 1) * GS_STAGEW) * 4;
            #pragma unroll
            for (int i = 0; i < 4; i++) {
                cp16(so + (uint32_t)(i * 32 * GS_STRIDE) * 4, ap + (size_t)(i * 32) * K);
                cp16(so + (uint32_t)(GS_AWORDS + i * 32 * GS_STRIDE) * 4, wp + (size_t)(i * 32) * K);
            }
            CP_COMMIT();
        }
        const uint32_t* sA = sm + buf * GS_STAGEW;
        const uint32_t* sB = sA + GS_AWORDS;
        #pragma unroll
        for (int ks = 0; ks < 4; ks++) {
            uint32_t af[4][4];
            #pragma unroll
            for (int mt = 0; mt < 4; mt++) {
                const uint32_t* p = sA + (wm * 64 + mt * 16 + r4) * GS_STRIDE + ks * 8 + c4;
                af[mt][0] = p[0];
                af[mt][1] = p[8 * GS_STRIDE];
                af[mt][2] = p[4];
                af[mt][3] = p[8 * GS_STRIDE + 4];
            }
            uint32_t bf[4][2];
            #pragma unroll
            for (int nt = 0; nt < 4; nt++) {
                const uint32_t* p = sB + (wn * 32 + nt * 8 + r4) * GS_STRIDE + ks * 8 + c4;
                bf[nt][0] = p[0];
                bf[nt][1] = p[4];
            }
            #pragma unroll
            for (int mt = 0; mt < 4; mt++)
                #pragma unroll
                for (int nt = 0; nt < 4; nt++)
                    mma_tf32(acc[mt][nt][0], acc[mt][nt][1], acc[mt][nt][2], acc[mt][nt][3],
                             af[mt][0], af[mt][1], af[mt][2], af[mt][3],
                             bf[nt][0], bf[nt][1]);
        }
    }

    // ---- epilogue ----
    #pragma unroll
    for (int mt = 0; mt < 4; mt++) {
        int gr = bm + wm * 64 + mt * 16 + r4;
        #pragma unroll
        for (int nt = 0; nt < 4; nt++) {
            int gc = bn + wn * 32 + nt * 8 + c4 * 2;
            float b0 = bias[gc], b1 = bias[gc + 1];
            float v[4];
            v[0] = acc[mt][nt][0] + b0;
            v[1] = acc[mt][nt][1] + b1;
            v[2] = acc[mt][nt][2] + b0;
            v[3] = acc[mt][nt][3] + b1;
            #pragma unroll
            for (int u = 0; u < 4; u++) {
                if (EPI == 1) v[u] = 0.5f * v[u] * (1.0f + erff(v[u] * 0.7071067811865476f));
                else if (EPI == 2) v[u] = v[u] > 0.0f ? v[u] : expm1f(v[u]);
                if (RND) v[u] = __uint_as_float(f2tf32(v[u]));
            }
            *(float2*)(C + (size_t)gr * ldc + gc)       = make_float2(v[0], v[1]);
            *(float2*)(C + (size_t)(gr + 8) * ldc + gc) = make_float2(v[2], v[3]);
        }
    }
}

// ---------------- relative position bias table ----------------
__global__ void pbias_kernel(const float* __restrict__ rel_embed, float* __restrict__ pb)
{
    int d = blockIdx.x * blockDim.x + threadIdx.x;
    if (d >= 2047) return;
    int rel = d - 1023;
    int bucket = (rel > 0) ? 160 : 0;
    int r = rel < 0 ? -rel : rel;
    int val;
    if (r < 80) {
        val = r;
    } else {
        float rf = (float)(r < 1 ? 1 : r);
        float t = logf(rf / 80.0f) / 2.3025851f * 80.0f;
        int large = 80 + (int)t;
        val = large < 159 ? large : 159;
    }
    bucket += val;
    #pragma unroll
    for (int h = 0; h < NHH; h++)
        pb[h * 2048 + d] = rel_embed[bucket * NHH + h];
}

// ---------------- gate kernel ----------------
__global__ void gate_kernel(const float* __restrict__ x, const float* __restrict__ Wg,
                            const float* __restrict__ bg, const float* __restrict__ gc,
                            float* __restrict__ gate)
{
    __shared__ float xs[HH];
    int bs = blockIdx.x;
    int t = threadIdx.x;
    for (int i = t; i < HH; i += 128) xs[i] = x[(size_t)bs * HH + i];
    __syncthreads();
    int h = t >> 3, e = t & 7;
    float acc = bg[e];
    const float* wrow = Wg + e * HDD;
    const float* xrow = xs + h * HDD;
    #pragma unroll 8
    for (int d = 0; d < HDD; d++) acc += xrow[d] * wrow[d];
    acc += __shfl_xor_sync(0xffffffffu, acc, 1);
    acc += __shfl_xor_sync(0xffffffffu, acc, 2);
    float other = __shfl_xor_sync(0xffffffffu, acc, 4);
    if (e == 0) {
        float p0 = acc, p1 = other;
        float ga = 1.0f / (1.0f + expf(-p0));
        float gb = 1.0f / (1.0f + expf(-p1));
        float go = ga * (gb * gc[h] - 1.0f) + 2.0f;
        int b = bs >> 10, s = bs & 1023;
        gate[(b * NHH + h) * SS + s] = go;
    }
}

// ================= tensor-core flash attention =================
// qkv: packed [M, 3072] tf32-rounded (q|k|v). ctx written tf32-rounded [M,1024].
#define AQS 68
#define AVS 72
#define ASM_WORDS (3*64*AQS + 64*AVS)
#define ASM_BYTES (ASM_WORDS*4)              // 70656

__global__ void __launch_bounds__(128, 3) attn_tc(const float* __restrict__ qkv,
                                                  const float* __restrict__ gate,
                                                  const float* __restrict__ pb,
                                                  float* __restrict__ ctx)
{
    extern __shared__ uint32_t as_[];
    uint32_t* Qs = as_;
    uint32_t* Ks = Qs + 64 * AQS;
    uint32_t* Ps = Ks + 64 * AQS;
    uint32_t* Vs = Ps + 64 * AQS;

    int tid = threadIdx.x, wid = tid >> 5, lane = tid & 31;
    int r4 = lane >> 2, c4 = lane & 3;
    int i0 = blockIdx.x * 64, h = blockIdx.y, b = blockIdx.z;

    const uint32_t* qb = (const uint32_t*)qkv + ((size_t)(b * SS + i0)) * QKVN + h * HDD;
    const uint32_t* kb = (const uint32_t*)qkv + ((size_t)(b * SS)) * QKVN + HH + h * HDD;
    const uint32_t* vb = (const uint32_t*)qkv + ((size_t)(b * SS)) * QKVN + 2 * HH + h * HDD;

    for (int idx = tid; idx < 64 * 16; idx += 128) {
        int r = idx >> 4, c = (idx & 15) << 2;
        *(uint4*)(Qs + r * AQS + c) = *(const uint4*)(qb + (size_t)r * QKVN + c);
    }
    __syncthreads();

    uint32_t qf[8][4];
    {
        const uint32_t* qp = Qs + (wid * 16 + r4) * AQS + c4;
        #pragma unroll
        for (int ks = 0; ks < 8; ks++) {
            qf[ks][0] = qp[ks * 8];
            qf[ks][1] = qp[8 * AQS + ks * 8];
            qf[ks][2] = qp[ks * 8 + 4];
            qf[ks][3] = qp[8 * AQS + ks * 8 + 4];
        }
    }

    float gate0 = gate[(b * NHH + h) * SS + i0 + wid * 16 + r4];
    float gate1 = gate[(b * NHH + h) * SS + i0 + wid * 16 + r4 + 8];
    const float* pbh = pb + h * 2048 + 1023 - (i0 + wid * 16 + r4);

    float m0 = -INFINITY, m1 = -INFINITY, l0 = 0.0f, l1 = 0.0f;
    float oa[8][4];
    #pragma unroll
    for (int nt = 0; nt < 8; nt++)
        #pragma unroll
        for (int u = 0; u < 4; u++) oa[nt][u] = 0.0f;

    uint32_t ksm = smem_u32(Ks);
    uint32_t vsm = smem_u32(Vs);

    for (int j0 = 0; j0 < SS; j0 += 64) {
        __syncthreads();
        for (int idx = tid; idx < 64 * 16; idx += 128) {
            int r = idx >> 4, c = (idx & 15) << 2;
            cp16(ksm + (uint32_t)(r * AQS + c) * 4, kb + (size_t)(j0 + r) * QKVN + c);
            cp16(vsm + (uint32_t)(r * AVS + c) * 4, vb + (size_t)(j0 + r) * QKVN + c);
        }
        CP_COMMIT();
        CP_WAIT(0);
        __syncthreads();

        float sf[8][4];
        #pragma unroll
        for (int nt = 0; nt < 8; nt++)
            #pragma unroll
            for (int u = 0; u < 4; u++) sf[nt][u] = 0.0f;
        #pragma unroll
        for (int ks = 0; ks < 8; ks++) {
            #pragma unroll
            for (int nt = 0; nt < 8; nt++) {
                const uint32_t* p = Ks + (nt * 8 + r4) * AQS + ks * 8 + c4;
                mma_tf32(sf[nt][0], sf[nt][1], sf[nt][2], sf[nt][3],
                         qf[ks][0], qf[ks][1], qf[ks][2], qf[ks][3],
                         p[0], p[4]);
            }
        }

        #pragma unroll
        for (int nt = 0; nt < 8; nt++) {
            int j = j0 + nt * 8 + 2 * c4;
            float pb0 = pbh[j];
            float pb1 = pbh[j + 1];
            float pb2 = pbh[j - 8];
            float pb3 = pbh[j - 7];
            sf[nt][0] = sf[nt][0] * 0.125f + gate0 * pb0;
            sf[nt][1] = sf[nt][1] * 0.125f + gate0 * pb1;
            sf[nt][2] = sf[nt][2] * 0.125f + gate1 * pb2;
            sf[nt][3] = sf[nt][3] * 0.125f + gate1 * pb3;
        }

        float mx0 = -INFINITY, mx1 = -INFINITY;
        #pragma unroll
        for (int nt = 0; nt < 8; nt++) {
            mx0 = fmaxf(mx0, fmaxf(sf[nt][0], sf[nt][1]));
            mx1 = fmaxf(mx1, fmaxf(sf[nt][2], sf[nt][3]));
        }
        mx0 = fmaxf(mx0, __shfl_xor_sync(0xffffffffu, mx0, 1));
        mx0 = fmaxf(mx0, __shfl_xor_sync(0xffffffffu, mx0, 2));
        mx1 = fmaxf(mx1, __shfl_xor_sync(0xffffffffu, mx1, 1));
        mx1 = fmaxf(mx1, __shfl_xor_sync(0xffffffffu, mx1, 2));
        float mn0 = fmaxf(m0, mx0), mn1 = fmaxf(m1, mx1);
        float a0 = __expf(m0 - mn0), a1 = __expf(m1 - mn1);

        float ls0 = 0.0f, ls1 = 0.0f;
        uint32_t* pr0 = Ps + (wid * 16 + r4) * AQS + 2 * c4;
        uint32_t* pr1 = pr0 + 8 * AQS;
        #pragma unroll
        for (int nt = 0; nt < 8; nt++) {
            float p0 = __expf(sf[nt][0] - mn0);
            float p1 = __expf(sf[nt][1] - mn0);
            float p2 = __expf(sf[nt][2] - mn1);
            float p3 = __expf(sf[nt][3] - mn1);
            ls0 += p0 + p1; ls1 += p2 + p3;
            pr0[nt * 8]     = f2tf32(p0);
            pr0[nt * 8 + 1] = f2tf32(p1);
            pr1[nt * 8]     = f2tf32(p2);
            pr1[nt * 8 + 1] = f2tf32(p3);
        }
        ls0 += __shfl_xor_sync(0xffffffffu, ls0, 1);
        ls0 += __shfl_xor_sync(0xffffffffu, ls0, 2);
        ls1 += __shfl_xor_sync(0xffffffffu, ls1, 1);
        ls1 += __shfl_xor_sync(0xffffffffu, ls1, 2);
        l0 = l0 * a0 + ls0;  l1 = l1 * a1 + ls1;
        m0 = mn0;  m1 = mn1;
        #pragma unroll
        for (int nt = 0; nt < 8; nt++) {
            oa[nt][0] *= a0; oa[nt][1] *= a0;
            oa[nt][2] *= a1; oa[nt][3] *= a1;
        }
        __syncwarp();

        const uint32_t* pp = Ps + (wid * 16 + r4) * AQS + c4;
        #pragma unroll
        for (int ks = 0; ks < 8; ks++) {
            uint32_t af0 = pp[ks * 8];
            uint32_t af1 = pp[8 * AQS + ks * 8];
            uint32_t af2 = pp[ks * 8 + 4];
            uint32_t af3 = pp[8 * AQS + ks * 8 + 4];
            #pragma unroll
            for (int nt = 0; nt < 8; nt++) {
                uint32_t b0 = Vs[(ks * 8 + c4) * AVS + nt * 8 + r4];
                uint32_t b1 = Vs[(ks * 8 + c4 + 4) * AVS + nt * 8 + r4];
                mma_tf32(oa[nt][0], oa[nt][1], oa[nt][2], oa[nt][3],
                         af0, af1, af2, af3, b0, b1);
            }
        }
    }

    float inv0 = 1.0f / l0, inv1 = 1.0f / l1;
    uint32_t* cb0 = (uint32_t*)ctx + ((size_t)(b * SS + i0 + wid * 16 + r4)) * HH + h * HDD;
    uint32_t* cb1 = cb0 + 8 * HH;
    #pragma unroll
    for (int nt = 0; nt < 8; nt++) {
        uint2 w0, w1;
        w0.x = f2tf32(oa[nt][0] * inv0);
        w0.y = f2tf32(oa[nt][1] * inv0);
        w1.x = f2tf32(oa[nt][2] * inv1);
        w1.y = f2tf32(oa[nt][3] * inv1);
        *(uint2*)(cb0 + nt * 8 + 2 * c4) = w0;
        *(uint2*)(cb1 + nt * 8 + 2 * c4) = w1;
    }
}

// ---------------- residual-add + LayerNorm (+ optional tf32 copy) ----------------
__global__ void ln_kernel(const float* __restrict__ A, const float* __restrict__ B,
                          const float* __restrict__ g, const float* __restrict__ bt,
                          float* __restrict__ out, float* __restrict__ out2)
{
    __shared__ float sm[8];
    int row = blockIdx.x;
    int t = threadIdx.x;
    size_t base = (size_t)row * HH;
    float vals[4];
    #pragma unroll
    for (int u = 0; u < 4; u++) {
        int i = t + u*256;
        vals[u] = A[base + i] + B[base + i];
    }
    float sum = vals[0] + vals[1] + vals[2] + vals[3];
    #pragma unroll
    for (int off = 16; off >= 1; off >>= 1) sum += __shfl_xor_sync(0xffffffffu, sum, off);
    if ((t & 31) == 0) sm[t >> 5] = sum;
    __syncthreads();
    float tot = 0.0f;
    #pragma unroll
    for (int w = 0; w < 8; w++) tot += sm[w];
    float mean = tot * (1.0f / HH);
    __syncthreads();
    float vs = 0.0f;
    #pragma unroll
    for (int u = 0; u < 4; u++) { float d = vals[u] - mean; vs += d * d; }
    #pragma unroll
    for (int off = 16; off >= 1; off >>= 1) vs += __shfl_xor_sync(0xffffffffu, vs, off);
    if ((t & 31) == 0) sm[t >> 5] = vs;
    __syncthreads();
    float vtot = 0.0f;
    #pragma unroll
    for (int w = 0; w < 8; w++) vtot += sm[w];
    float rstd = rsqrtf(vtot * (1.0f / HH) + EPSF);
    #pragma unroll
    for (int u = 0; u < 4; u++) {
        int i = t + u*256;
        float r = (vals[u] - mean) * rstd * g[i] + bt[i];
        out[base + i] = r;
        if (out2) out2[base + i] = __uint_as_float(f2tf32(r));
    }
}

// ---------------- launch ----------------
extern "C" void kernel_launch(void* const* d_in, const int* in_sizes, int n_in,
                              void* d_out, int out_size)
{
    const float* x   = (const float*)d_in[0];
    const float* Wq  = (const float*)d_in[1];
    const float* bq  = (const float*)d_in[2];
    const float* Wk  = (const float*)d_in[3];
    const float* bk  = (const float*)d_in[4];
    const float* Wv  = (const float*)d_in[5];
    const float* bv  = (const float*)d_in[6];
    const float* Wo  = (const float*)d_in[7];
    const float* bo  = (const float*)d_in[8];
    const float* Wg  = (const float*)d_in[9];
    const float* bg  = (const float*)d_in[10];
    const float* gru = (const float*)d_in[11];
    const float* rel = (const float*)d_in[12];
    const float* l1g = (const float*)d_in[13];
    const float* l1b = (const float*)d_in[14];
    const float* W1  = (const float*)d_in[15];
    const float* b1  = (const float*)d_in[16];
    const float* W2  = (const float*)d_in[17];
    const float* b2  = (const float*)d_in[18];
    const float* l2g = (const float*)d_in[19];
    const float* l2b = (const float*)d_in[20];
    const float* Wad = (const float*)d_in[21];
    const float* bad = (const float*)d_in[22];
    const float* Wau = (const float*)d_in[23];
    const float* bau = (const float*)d_in[24];
    float* out = (float*)d_out;

    float *pqkv, *pctx, *patt, *ph, *phr, *pff1, *pff2, *pgate, *ppb;
    float *pxr, *pwqkv, *pwo, *pw1, *pw2c, *pwad, *pbqkv, *pb2c;
    cudaGetSymbolAddress((void**)&pqkv, g_qkv);
    cudaGetSymbolAddress((void**)&pctx, g_ctx);
    cudaGetSymbolAddress((void**)&patt, g_att);
    cudaGetSymbolAddress((void**)&ph,   g_h);
    cudaGetSymbolAddress((void**)&phr,  g_hr);
    cudaGetSymbolAddress((void**)&pff1, g_ff1);
    cudaGetSymbolAddress((void**)&pff2, g_ff2);
    cudaGetSymbolAddress((void**)&pgate, g_gate);
    cudaGetSymbolAddress((void**)&ppb,  g_pb);
    cudaGetSymbolAddress((void**)&pxr,  g_xr);
    cudaGetSymbolAddress((void**)&pwqkv, g_wqkv);
    cudaGetSymbolAddress((void**)&pwo,  g_wo);
    cudaGetSymbolAddress((void**)&pw1,  g_w1);
    cudaGetSymbolAddress((void**)&pw2c, g_w2c);
    cudaGetSymbolAddress((void**)&pwad, g_wad);
    cudaGetSymbolAddress((void**)&pbqkv, g_bqkv);
    cudaGetSymbolAddress((void**)&pb2c, g_b2c);

    cudaFuncSetAttribute(gemm_tc<0,0>, cudaFuncAttributeMaxDynamicSharedMemorySize, GS_BYTES);
    cudaFuncSetAttribute(gemm_tc<0,1>, cudaFuncAttributeMaxDynamicSharedMemorySize, GS_BYTES);
    cudaFuncSetAttribute(gemm_tc<1,1>, cudaFuncAttributeMaxDynamicSharedMemorySize, GS_BYTES);
    cudaFuncSetAttribute(gemm_tc<2,1>, cudaFuncAttributeMaxDynamicSharedMemorySize, GS_BYTES);
    cudaFuncSetAttribute(attn_tc, cudaFuncAttributeMaxDynamicSharedMemorySize, ASM_BYTES);

    // 0) pre-round all GEMM operands to tf32
    round_tf32<<<(MM*HH)/1024, 256>>>(x,  (uint32_t*)pxr, MM*HH);
    round_tf32<<<(HH*HH)/1024, 256>>>(Wq, (uint32_t*)pwqkv,            HH*HH);
    round_tf32<<<(HH*HH)/1024, 256>>>(Wk, (uint32_t*)pwqkv + HH*HH,    HH*HH);
    round_tf32<<<(HH*HH)/1024, 256>>>(Wv, (uint32_t*)pwqkv + 2*HH*HH,  HH*HH);
    round_tf32<<<(HH*HH)/1024, 256>>>(Wo, (uint32_t*)pwo, HH*HH);
    round_tf32<<<(FFF*HH)/1024, 256>>>(W1, (uint32_t*)pw1, FFF*HH);
    round_tf32<<<(ADD*HH)/1024, 256>>>(Wad, (uint32_t*)pwad, ADD*HH);
    // W2 | Wau row-interleaved into [1024, 4352]
    round_tf32_pitch<<<(HH*FFF)/1024, 256>>>(W2,  (uint32_t*)pw2c,        HH, FFF, FAK);
    round_tf32_pitch<<<(HH*ADD)/1024, 256>>>(Wau, (uint32_t*)pw2c + FFF,  HH, ADD, FAK);
    // biases: qkv concat, b2+bau sum
    cudaMemcpyAsync(pbqkv,          bq, HH*4, cudaMemcpyDeviceToDevice, 0);
    cudaMemcpyAsync(pbqkv + HH,     bk, HH*4, cudaMemcpyDeviceToDevice, 0);
    cudaMemcpyAsync(pbqkv + 2*HH,   bv, HH*4, cudaMemcpyDeviceToDevice, 0);
    bias_sum<<<4, 256>>>(b2, bau, pb2c, HH);

    // 1) relative position bias table
    pbias_kernel<<<(2047 + 127) / 128, 128>>>(rel, ppb);
    // 2) gates
    gate_kernel<<<BB * SS, 128>>>(x, Wg, bg, gru, pgate);
    // 3) fused QKV projection -> packed [M, 3072], tf32-rounded
    gemm_tc<0,1><<<dim3(QKVN/128, MM/128), 256, GS_BYTES>>>(pxr, pwqkv, pbqkv, pqkv, MM, QKVN, HH, QKVN);
    // 4) attention
    attn_tc<<<dim3(SS/64, NHH, BB), 128, ASM_BYTES>>>(pqkv, pgate, ppb, pctx);
    // 5) output projection
    gemm_tc<0,0><<<dim3(HH/128, MM/128), 256, GS_BYTES>>>(pctx, pwo, bo, patt, MM, HH, HH, HH);
    // 6) residual + LN1 (h fp32 + tf32 copy)
    ln_kernel<<<MM, 256>>>(x, patt, l1g, l1b, ph, phr);
    // 7) FFN up (gelu) -> cols [0,4096) of [M,4352];  adapter down (elu) -> cols [4096,4352)
    gemm_tc<1,1><<<dim3(FFF/128, MM/128), 256, GS_BYTES>>>(phr, pw1, b1, pff1, MM, FFF, HH, FAK);
    gemm_tc<2,1><<<dim3(ADD/128, MM/128), 256, GS_BYTES>>>(phr, pwad, bad, pff1 + FFF, MM, ADD, HH, FAK);
    // 8) fused FFN down + adapter up: [M,4352] @ [1024,4352]^T + (b2+bau)
    gemm_tc<0,0><<<dim3(HH/128, MM/128), 256, GS_BYTES>>>(pff1, pw2c, pb2c, pff2, MM, HH, FAK, HH);
    // 9) h + (ff+adapt), LN2 -> out
    ln_kernel<<<MM, 256>>>(ph, pff2, l2g, l2b, out, nullptr);
}

// round 6
// speedup vs baseline: 5.2785x; 1.4480x over previous
#include <cuda_runtime.h>
#include <cuda_fp16.h>
#include <math.h>
#include <stdint.h>

// ---------------- problem constants ----------------
#define BB   4
#define SS   1024
#define HH   1024
#define NHH  16
#define HDD  64
#define FFF  4096
#define ADD  256
#define MM   (BB*SS)          // 4096 rows
#define EPSF 1e-5f
#define QKVN 3072
#define FAK  (FFF+ADD)        // 4352

// ---------------- scratch ----------------
__device__ __half g_qkv [(size_t)MM*QKVN];
__device__ __half g_ctx [MM*HH];
__device__ float  g_att [MM*HH];
__device__ float  g_h   [MM*HH];
__device__ __half g_hr  [MM*HH];
__device__ __half g_ff1 [(size_t)MM*FAK];
__device__ float  g_ff2 [MM*HH];
__device__ float  g_gate[BB*NHH*SS];
__device__ float  g_pb  [NHH*2048];
// fp16 operand copies
__device__ __half g_xr  [MM*HH];
__device__ __half g_wqkv[QKVN*HH];
__device__ __half g_wo  [HH*HH];
__device__ __half g_w1  [(size_t)FFF*HH];
__device__ __half g_w2c [(size_t)HH*FAK];
__device__ __half g_wad [ADD*HH];
__device__ float  g_bqkv[QKVN];
__device__ float  g_b2c [HH];

// ---------------- helpers ----------------
__device__ __forceinline__ uint32_t smem_u32(const void* p) {
    uint32_t a;
    asm("{ .reg .u64 t; cvta.to.shared.u64 t, %1; cvt.u32.u64 %0, t; }" : "=r"(a) : "l"(p));
    return a;
}
__device__ __forceinline__ void cp16(uint32_t s, const void* g) {
    asm volatile("cp.async.cg.shared.global [%0], [%1], 16;" :: "r"(s), "l"(g));
}
#define CP_COMMIT() asm volatile("cp.async.commit_group;")
#define CP_WAIT(N)  asm volatile("cp.async.wait_group %0;" :: "n"(N))

__device__ __forceinline__ void mma_f16(float& c0, float& c1, float& c2, float& c3,
                                        uint32_t a0, uint32_t a1, uint32_t a2, uint32_t a3,
                                        uint32_t b0, uint32_t b1) {
    asm volatile(
        "mma.sync.aligned.m16n8k16.row.col.f32.f16.f16.f32 "
        "{%0,%1,%2,%3}, {%4,%5,%6,%7}, {%8,%9}, {%0,%1,%2,%3};\n"
        : "+f"(c0), "+f"(c1), "+f"(c2), "+f"(c3)
        : "r"(a0), "r"(a1), "r"(a2), "r"(a3), "r"(b0), "r"(b1));
}
__device__ __forceinline__ void ldsm_x2_trans(uint32_t& b0, uint32_t& b1, uint32_t addr) {
    asm volatile("ldmatrix.sync.aligned.m8n8.x2.trans.shared.b16 {%0,%1}, [%2];"
                 : "=r"(b0), "=r"(b1) : "r"(addr));
}
__device__ __forceinline__ uint32_t packh2(float a, float b) {
    __half2 h = __floats2half2_rn(a, b);
    return *(uint32_t*)&h;
}

// ---------------- f32 -> f16 pack (contiguous) ----------------
__global__ void pack_h(const float* __restrict__ in, __half* __restrict__ out, int n)
{
    int i = (blockIdx.x * 256 + threadIdx.x) * 8;
    if (i >= n) return;
    float4 a = *(const float4*)(in + i);
    float4 b = *(const float4*)(in + i + 4);
    uint4 o;
    o.x = packh2(a.x, a.y); o.y = packh2(a.z, a.w);
    o.z = packh2(b.x, b.y); o.w = packh2(b.z, b.w);
    *(uint4*)(out + i) = o;
}
// ---------------- f32 -> f16 pack (strided output) ----------------
__global__ void pack_h_pitch(const float* __restrict__ in, __half* __restrict__ out,
                             int rows, int cols, int ldo)
{
    int i = (blockIdx.x * 256 + threadIdx.x) * 8;
    if (i >= rows * cols) return;
    int row = i / cols, col = i - row * cols;
    float4 a = *(const float4*)(in + (size_t)row * cols + col);
    float4 b = *(const float4*)(in + (size_t)row * cols + col + 4);
    uint4 o;
    o.x = packh2(a.x, a.y); o.y = packh2(a.z, a.w);
    o.z = packh2(b.x, b.y); o.w = packh2(b.z, b.w);
    *(uint4*)(out + (size_t)row * ldo + col) = o;
}
__global__ void bias_sum(const float* __restrict__ a, const float* __restrict__ b,
                         float* __restrict__ o, int n)
{
    int i = blockIdx.x * 256 + threadIdx.x;
    if (i < n) o[i] = a[i] + b[i];
}

// ================= fp16 mma.sync GEMM (cp.async pipelined) =================
// A[M,K], W[N,K] half; C = A @ W^T + bias. BM=BN=128, BK=32.
// Smem rows: 16 data words (32 halves) + 4 pad = stride 20 words.
#define HS_STRIDE 20
#define HS_AWORDS (128*HS_STRIDE)
#define HS_STAGEW (2*HS_AWORDS)
#define HS_BYTES  (2*HS_STAGEW*4)   // 40960

template<int EPI, int OUTH>   // EPI: 0=none,1=gelu,2=elu ; OUTH: 1=half out, 0=float out
__global__ void __launch_bounds__(256, 2) gemm_h(const __half* __restrict__ A,
                                                 const __half* __restrict__ W,
                                                 const float* __restrict__ bias,
                                                 void* __restrict__ C,
                                                 int M, int N, int K, int ldc)
{
    extern __shared__ uint32_t sm[];
    int tid  = threadIdx.x;
    int wid  = tid >> 5, lane = tid & 31;
    int wm   = wid >> 2;          // 0..1
    int wn   = wid & 3;           // 0..3
    int bm = blockIdx.y * 128, bn = blockIdx.x * 128;
    int r4 = lane >> 2;
    int c4 = lane & 3;

    float acc[4][4][4];
    #pragma unroll
    for (int mt = 0; mt < 4; mt++)
        #pragma unroll
        for (int nt = 0; nt < 4; nt++)
            #pragma unroll
            for (int u = 0; u < 4; u++) acc[mt][nt][u] = 0.0f;

    int lrow = tid >> 2;            // 0..63
    int lcc  = tid & 3;             // chunk 0..3 (16B = 8 halves)
    const __half* aptr = A + (size_t)(bm + lrow) * K + lcc * 8;
    const __half* wptr = W + (size_t)(bn + lrow) * K + lcc * 8;
    uint32_t sb = smem_u32(sm);
    uint32_t sa_base = sb + (uint32_t)(lrow * HS_STRIDE + lcc * 4) * 4;

    int T = K >> 5;

    // prologue: tile 0 -> buf 0
    #pragma unroll
    for (int i = 0; i < 2; i++) {
        cp16(sa_base + (uint32_t)(i * 64 * HS_STRIDE) * 4, aptr + (size_t)(i * 64) * K);
        cp16(sa_base + (uint32_t)(HS_AWORDS + i * 64 * HS_STRIDE) * 4, wptr + (size_t)(i * 64) * K);
    }
    CP_COMMIT();

    for (int k0 = 0; k0 < T; k0++) {
        int buf = k0 & 1;
        CP_WAIT(0);
        __syncthreads();
        if (k0 + 1 < T) {
            const __half* ap = aptr + (k0 + 1) * 32;
            const __half* wp = wptr + (k0 + 1) * 32;
            uint32_t so = sa_base + (uint32_t)((buf ^ 1) * HS_STAGEW) * 4;
            #pragma unroll
            for (int i = 0; i < 2; i++) {
                cp16(so + (uint32_t)(i * 64 * HS_STRIDE) * 4, ap + (size_t)(i * 64) * K);
                cp16(so + (uint32_t)(HS_AWORDS + i * 64 * HS_STRIDE) * 4, wp + (size_t)(i * 64) * K);
            }
            CP_COMMIT();
        }
        const uint32_t* sA = sm + buf * HS_STAGEW;
        const uint32_t* sB = sA + HS_AWORDS;
        #pragma unroll
        for (int ks = 0; ks < 2; ks++) {       // two k16 steps
            uint32_t af[4][4];
            #pragma unroll
            for (int mt = 0; mt < 4; mt++) {
                const uint32_t* p = sA + (wm * 64 + mt * 16 + r4) * HS_STRIDE + ks * 8 + c4;
                af[mt][0] = p[0];
                af[mt][1] = p[8 * HS_STRIDE];
                af[mt][2] = p[4];
                af[mt][3] = p[8 * HS_STRIDE + 4];
            }
            uint32_t bf[4][2];
            #pragma unroll
            for (int nt = 0; nt < 4; nt++) {
                const uint32_t* p = sB + (wn * 32 + nt * 8 + r4) * HS_STRIDE + ks * 8 + c4;
                bf[nt][0] = p[0];
                bf[nt][1] = p[4];
            }
            #pragma unroll
            for (int mt = 0; mt < 4; mt++)
                #pragma unroll
                for (int nt = 0; nt < 4; nt++)
                    mma_f16(acc[mt][nt][0], acc[mt][nt][1], acc[mt][nt][2], acc[mt][nt][3],
                            af[mt][0], af[mt][1], af[mt][2], af[mt][3],
                            bf[nt][0], bf[nt][1]);
        }
    }

    // ---- epilogue ----
    #pragma unroll
    for (int mt = 0; mt < 4; mt++) {
        int gr = bm + wm * 64 + mt * 16 + r4;
        #pragma unroll
        for (int nt = 0; nt < 4; nt++) {
            int gc = bn + wn * 32 + nt * 8 + c4 * 2;
            float b0 = bias[gc], b1 = bias[gc + 1];
            float v[4];
            v[0] = acc[mt][nt][0] + b0;
            v[1] = acc[mt][nt][1] + b1;
            v[2] = acc[mt][nt][2] + b0;
            v[3] = acc[mt][nt][3] + b1;
            #pragma unroll
            for (int u = 0; u < 4; u++) {
                if (EPI == 1) v[u] = 0.5f * v[u] * (1.0f + erff(v[u] * 0.7071067811865476f));
                else if (EPI == 2) v[u] = v[u] > 0.0f ? v[u] : expm1f(v[u]);
            }
            if (OUTH) {
                __half* Ch = (__half*)C;
                *(uint32_t*)(Ch + (size_t)gr * ldc + gc)       = packh2(v[0], v[1]);
                *(uint32_t*)(Ch + (size_t)(gr + 8) * ldc + gc) = packh2(v[2], v[3]);
            } else {
                float* Cf = (float*)C;
                *(float2*)(Cf + (size_t)gr * ldc + gc)       = make_float2(v[0], v[1]);
                *(float2*)(Cf + (size_t)(gr + 8) * ldc + gc) = make_float2(v[2], v[3]);
            }
        }
    }
}

// ---------------- relative position bias table ----------------
__global__ void pbias_kernel(const float* __restrict__ rel_embed, float* __restrict__ pb)
{
    int d = blockIdx.x * blockDim.x + threadIdx.x;
    if (d >= 2047) return;
    int rel = d - 1023;
    int bucket = (rel > 0) ? 160 : 0;
    int r = rel < 0 ? -rel : rel;
    int val;
    if (r < 80) {
        val = r;
    } else {
        float rf = (float)(r < 1 ? 1 : r);
        float t = logf(rf / 80.0f) / 2.3025851f * 80.0f;
        int large = 80 + (int)t;
        val = large < 159 ? large : 159;
    }
    bucket += val;
    #pragma unroll
    for (int h = 0; h < NHH; h++)
        pb[h * 2048 + d] = rel_embed[bucket * NHH + h];
}

// ---------------- gate kernel ----------------
__global__ void gate_kernel(const float* __restrict__ x, const float* __restrict__ Wg,
                            const float* __restrict__ bg, const float* __restrict__ gc,
                            float* __restrict__ gate)
{
    __shared__ float xs[HH];
    int bs = blockIdx.x;
    int t = threadIdx.x;
    for (int i = t; i < HH; i += 128) xs[i] = x[(size_t)bs * HH + i];
    __syncthreads();
    int h = t >> 3, e = t & 7;
    float acc = bg[e];
    const float* wrow = Wg + e * HDD;
    const float* xrow = xs + h * HDD;
    #pragma unroll 8
    for (int d = 0; d < HDD; d++) acc += xrow[d] * wrow[d];
    acc += __shfl_xor_sync(0xffffffffu, acc, 1);
    acc += __shfl_xor_sync(0xffffffffu, acc, 2);
    float other = __shfl_xor_sync(0xffffffffu, acc, 4);
    if (e == 0) {
        float p0 = acc, p1 = other;
        float ga = 1.0f / (1.0f + expf(-p0));
        float gb = 1.0f / (1.0f + expf(-p1));
        float go = ga * (gb * gc[h] - 1.0f) + 2.0f;
        int b = bs >> 10, s = bs & 1023;
        gate[(b * NHH + h) * SS + s] = go;
    }
}

// ================= fp16 tensor-core flash attention =================
// qkv: packed [M,3072] half. ctx out half [M,1024].
// Smem rows: 32 data words (64 halves) + 4 pad = stride 36 words.
#define AS 36
#define ATT_WORDS (4*64*AS)
#define ATT_BYTES (ATT_WORDS*4)    // 36864

__global__ void __launch_bounds__(128, 3) attn_tc(const __half* __restrict__ qkv,
                                                  const float* __restrict__ gate,
                                                  const float* __restrict__ pb,
                                                  __half* __restrict__ ctx)
{
    extern __shared__ uint32_t as_[];
    uint32_t* Qs = as_;
    uint32_t* Ks = Qs + 64 * AS;
    uint32_t* Ps = Ks + 64 * AS;
    uint32_t* Vs = Ps + 64 * AS;

    int tid = threadIdx.x, wid = tid >> 5, lane = tid & 31;
    int r4 = lane >> 2, c4 = lane & 3;
    int i0 = blockIdx.x * 64, h = blockIdx.y, b = blockIdx.z;

    const __half* qb = qkv + ((size_t)(b * SS + i0)) * QKVN + h * HDD;
    const __half* kb = qkv + ((size_t)(b * SS)) * QKVN + HH + h * HDD;
    const __half* vb = qkv + ((size_t)(b * SS)) * QKVN + 2 * HH + h * HDD;

    // ---- load Q tile (64 rows x 64 halves) ----
    for (int idx = tid; idx < 64 * 8; idx += 128) {
        int r = idx >> 3, cc = idx & 7;      // cc: 16B chunk = 8 halves
        *(uint4*)(Qs + r * AS + cc * 4) = *(const uint4*)(qb + (size_t)r * QKVN + cc * 8);
    }
    __syncthreads();

    // ---- Q fragments: 4 k16 chunks ----
    uint32_t qf[4][4];
    {
        const uint32_t* qp = Qs + (wid * 16 + r4) * AS + c4;
        #pragma unroll
        for (int ks = 0; ks < 4; ks++) {
            qf[ks][0] = qp[ks * 8];
            qf[ks][1] = qp[8 * AS + ks * 8];
            qf[ks][2] = qp[ks * 8 + 4];
            qf[ks][3] = qp[8 * AS + ks * 8 + 4];
        }
    }

    float gate0 = gate[(b * NHH + h) * SS + i0 + wid * 16 + r4];
    float gate1 = gate[(b * NHH + h) * SS + i0 + wid * 16 + r4 + 8];
    const float* pbh = pb + h * 2048 + 1023 - (i0 + wid * 16 + r4);

    float m0 = -INFINITY, m1 = -INFINITY, l0 = 0.0f, l1 = 0.0f;
    float oa[8][4];
    #pragma unroll
    for (int nt = 0; nt < 8; nt++)
        #pragma unroll
        for (int u = 0; u < 4; u++) oa[nt][u] = 0.0f;

    uint32_t ksm = smem_u32(Ks);
    uint32_t vsm = smem_u32(Vs);
    uint32_t vls = vsm + (uint32_t)(lane & 15) * AS * 4;   // ldmatrix lane base

    for (int j0 = 0; j0 < SS; j0 += 64) {
        __syncthreads();
        for (int idx = tid; idx < 64 * 8; idx += 128) {
            int r = idx >> 3, cc = idx & 7;
            cp16(ksm + (uint32_t)(r * AS + cc * 4) * 4, kb + (size_t)(j0 + r) * QKVN + cc * 8);
            cp16(vsm + (uint32_t)(r * AS + cc * 4) * 4, vb + (size_t)(j0 + r) * QKVN + cc * 8);
        }
        CP_COMMIT();
        CP_WAIT(0);
        __syncthreads();

        // ---- S = Q K^T ----
        float sf[8][4];
        #pragma unroll
        for (int nt = 0; nt < 8; nt++)
            #pragma unroll
            for (int u = 0; u < 4; u++) sf[nt][u] = 0.0f;
        #pragma unroll
        for (int ks = 0; ks < 4; ks++) {
            #pragma unroll
            for (int nt = 0; nt < 8; nt++) {
                const uint32_t* p = Ks + (nt * 8 + r4) * AS + ks * 8 + c4;
                mma_f16(sf[nt][0], sf[nt][1], sf[nt][2], sf[nt][3],
                        qf[ks][0], qf[ks][1], qf[ks][2], qf[ks][3],
                        p[0], p[4]);
            }
        }

        // ---- scale + gated relative bias ----
        #pragma unroll
        for (int nt = 0; nt < 8; nt++) {
            int j = j0 + nt * 8 + 2 * c4;
            float pb0 = pbh[j];
            float pb1 = pbh[j + 1];
            float pb2 = pbh[j - 8];
            float pb3 = pbh[j - 7];
            sf[nt][0] = sf[nt][0] * 0.125f + gate0 * pb0;
            sf[nt][1] = sf[nt][1] * 0.125f + gate0 * pb1;
            sf[nt][2] = sf[nt][2] * 0.125f + gate1 * pb2;
            sf[nt][3] = sf[nt][3] * 0.125f + gate1 * pb3;
        }

        // ---- online softmax ----
        float mx0 = -INFINITY, mx1 = -INFINITY;
        #pragma unroll
        for (int nt = 0; nt < 8; nt++) {
            mx0 = fmaxf(mx0, fmaxf(sf[nt][0], sf[nt][1]));
            mx1 = fmaxf(mx1, fmaxf(sf[nt][2], sf[nt][3]));
        }
        mx0 = fmaxf(mx0, __shfl_xor_sync(0xffffffffu, mx0, 1));
        mx0 = fmaxf(mx0, __shfl_xor_sync(0xffffffffu, mx0, 2));
        mx1 = fmaxf(mx1, __shfl_xor_sync(0xffffffffu, mx1, 1));
        mx1 = fmaxf(mx1, __shfl_xor_sync(0xffffffffu, mx1, 2));
        float mn0 = fmaxf(m0, mx0), mn1 = fmaxf(m1, mx1);
        float a0 = __expf(m0 - mn0), a1 = __expf(m1 - mn1);

        float ls0 = 0.0f, ls1 = 0.0f;
        uint32_t* pr0 = Ps + (wid * 16 + r4) * AS + c4;
        uint32_t* pr1 = pr0 + 8 * AS;
        #pragma unroll
        for (int nt = 0; nt < 8; nt++) {
            float p0 = __expf(sf[nt][0] - mn0);
            float p1 = __expf(sf[nt][1] - mn0);
            float p2 = __expf(sf[nt][2] - mn1);
            float p3 = __expf(sf[nt][3] - mn1);
            ls0 += p0 + p1; ls1 += p2 + p3;
            pr0[nt * 4] = packh2(p0, p1);     // word (nt*8+2c4)/2 = nt*4 + c4
            pr1[nt * 4] = packh2(p2, p3);
        }
        ls0 += __shfl_xor_sync(0xffffffffu, ls0, 1);
        ls0 += __shfl_xor_sync(0xffffffffu, ls0, 2);
        ls1 += __shfl_xor_sync(0xffffffffu, ls1, 1);
        ls1 += __shfl_xor_sync(0xffffffffu, ls1, 2);
        l0 = l0 * a0 + ls0;  l1 = l1 * a1 + ls1;
        m0 = mn0;  m1 = mn1;
        #pragma unroll
        for (int nt = 0; nt < 8; nt++) {
            oa[nt][0] *= a0; oa[nt][1] *= a0;
            oa[nt][2] *= a1; oa[nt][3] *= a1;
        }
        __syncwarp();

        // ---- O += P V  (V transposed on the fly via ldmatrix.trans) ----
        const uint32_t* pp = Ps + (wid * 16 + r4) * AS + c4;
        #pragma unroll
        for (int ks = 0; ks < 4; ks++) {       // k16 chunks over j
            uint32_t af0 = pp[ks * 8];
            uint32_t af1 = pp[8 * AS + ks * 8];
            uint32_t af2 = pp[ks * 8 + 4];
            uint32_t af3 = pp[8 * AS + ks * 8 + 4];
            uint32_t vrow = vls + (uint32_t)(ks * 16) * AS * 4;
            #pragma unroll
            for (int nt = 0; nt < 8; nt++) {
                uint32_t b0, b1;
                ldsm_x2_trans(b0, b1, vrow + nt * 16);
                mma_f16(oa[nt][0], oa[nt][1], oa[nt][2], oa[nt][3],
                        af0, af1, af2, af3, b0, b1);
            }
        }
    }

    // ---- epilogue ----
    float inv0 = 1.0f / l0, inv1 = 1.0f / l1;
    __half* cb0 = ctx + ((size_t)(b * SS + i0 + wid * 16 + r4)) * HH + h * HDD;
    __half* cb1 = cb0 + 8 * HH;
    #pragma unroll
    for (int nt = 0; nt < 8; nt++) {
        *(uint32_t*)(cb0 + nt * 8 + 2 * c4) = packh2(oa[nt][0] * inv0, oa[nt][1] * inv0);
        *(uint32_t*)(cb1 + nt * 8 + 2 * c4) = packh2(oa[nt][2] * inv1, oa[nt][3] * inv1);
    }
}

// ---------------- residual-add + LayerNorm (+ optional half copy) ----------------
__global__ void ln_kernel(const float* __restrict__ A, const float* __restrict__ B,
                          const float* __restrict__ g, const float* __restrict__ bt,
                          float* __restrict__ out, __half* __restrict__ out2)
{
    __shared__ float sm[8];
    int row = blockIdx.x;
    int t = threadIdx.x;
    size_t base = (size_t)row * HH;
    float vals[4];
    #pragma unroll
    for (int u = 0; u < 4; u++) {
        int i = t + u*256;
        vals[u] = A[base + i] + B[base + i];
    }
    float sum = vals[0] + vals[1] + vals[2] + vals[3];
    #pragma unroll
    for (int off = 16; off >= 1; off >>= 1) sum += __shfl_xor_sync(0xffffffffu, sum, off);
    if ((t & 31) == 0) sm[t >> 5] = sum;
    __syncthreads();
    float tot = 0.0f;
    #pragma unroll
    for (int w = 0; w < 8; w++) tot += sm[w];
    float mean = tot * (1.0f / HH);
    __syncthreads();
    float vs = 0.0f;
    #pragma unroll
    for (int u = 0; u < 4; u++) { float d = vals[u] - mean; vs += d * d; }
    #pragma unroll
    for (int off = 16; off >= 1; off >>= 1) vs += __shfl_xor_sync(0xffffffffu, vs, off);
    if ((t & 31) == 0) sm[t >> 5] = vs;
    __syncthreads();
    float vtot = 0.0f;
    #pragma unroll
    for (int w = 0; w < 8; w++) vtot += sm[w];
    float rstd = rsqrtf(vtot * (1.0f / HH) + EPSF);
    #pragma unroll
    for (int u = 0; u < 4; u++) {
        int i = t + u*256;
        float r = (vals[u] - mean) * rstd * g[i] + bt[i];
        out[base + i] = r;
        if (out2) out2[base + i] = __float2half_rn(r);
    }
}

// ---------------- launch ----------------
extern "C" void kernel_launch(void* const* d_in, const int* in_sizes, int n_in,
                              void* d_out, int out_size)
{
    const float* x   = (const float*)d_in[0];
    const float* Wq  = (const float*)d_in[1];
    const float* bq  = (const float*)d_in[2];
    const float* Wk  = (const float*)d_in[3];
    const float* bk  = (const float*)d_in[4];
    const float* Wv  = (const float*)d_in[5];
    const float* bv  = (const float*)d_in[6];
    const float* Wo  = (const float*)d_in[7];
    const float* bo  = (const float*)d_in[8];
    const float* Wg  = (const float*)d_in[9];
    const float* bg  = (const float*)d_in[10];
    const float* gru = (const float*)d_in[11];
    const float* rel = (const float*)d_in[12];
    const float* l1g = (const float*)d_in[13];
    const float* l1b = (const float*)d_in[14];
    const float* W1  = (const float*)d_in[15];
    const float* b1  = (const float*)d_in[16];
    const float* W2  = (const float*)d_in[17];
    const float* b2  = (const float*)d_in[18];
    const float* l2g = (const float*)d_in[19];
    const float* l2b = (const float*)d_in[20];
    const float* Wad = (const float*)d_in[21];
    const float* bad = (const float*)d_in[22];
    const float* Wau = (const float*)d_in[23];
    const float* bau = (const float*)d_in[24];
    float* out = (float*)d_out;

    __half *pqkv, *pctx, *phr, *pff1, *pxr, *pwqkv, *pwo, *pw1, *pw2c, *pwad;
    float *patt, *ph, *pff2, *pgate, *ppb, *pbqkv, *pb2c;
    cudaGetSymbolAddress((void**)&pqkv, g_qkv);
    cudaGetSymbolAddress((void**)&pctx, g_ctx);
    cudaGetSymbolAddress((void**)&patt, g_att);
    cudaGetSymbolAddress((void**)&ph,   g_h);
    cudaGetSymbolAddress((void**)&phr,  g_hr);
    cudaGetSymbolAddress((void**)&pff1, g_ff1);
    cudaGetSymbolAddress((void**)&pff2, g_ff2);
    cudaGetSymbolAddress((void**)&pgate, g_gate);
    cudaGetSymbolAddress((void**)&ppb,  g_pb);
    cudaGetSymbolAddress((void**)&pxr,  g_xr);
    cudaGetSymbolAddress((void**)&pwqkv, g_wqkv);
    cudaGetSymbolAddress((void**)&pwo,  g_wo);
    cudaGetSymbolAddress((void**)&pw1,  g_w1);
    cudaGetSymbolAddress((void**)&pw2c, g_w2c);
    cudaGetSymbolAddress((void**)&pwad, g_wad);
    cudaGetSymbolAddress((void**)&pbqkv, g_bqkv);
    cudaGetSymbolAddress((void**)&pb2c, g_b2c);

    cudaFuncSetAttribute(gemm_h<0,0>, cudaFuncAttributeMaxDynamicSharedMemorySize, HS_BYTES);
    cudaFuncSetAttribute(gemm_h<0,1>, cudaFuncAttributeMaxDynamicSharedMemorySize, HS_BYTES);
    cudaFuncSetAttribute(gemm_h<1,1>, cudaFuncAttributeMaxDynamicSharedMemorySize, HS_BYTES);
    cudaFuncSetAttribute(gemm_h<2,1>, cudaFuncAttributeMaxDynamicSharedMemorySize, HS_BYTES);
    cudaFuncSetAttribute(attn_tc, cudaFuncAttributeMaxDynamicSharedMemorySize, ATT_BYTES);

    // 0) pack all GEMM operands to fp16
    pack_h<<<(MM*HH)/2048, 256>>>(x,  pxr, MM*HH);
    pack_h<<<(HH*HH)/2048, 256>>>(Wq, pwqkv,           HH*HH);
    pack_h<<<(HH*HH)/2048, 256>>>(Wk, pwqkv + HH*HH,   HH*HH);
    pack_h<<<(HH*HH)/2048, 256>>>(Wv, pwqkv + 2*HH*HH, HH*HH);
    pack_h<<<(HH*HH)/2048, 256>>>(Wo, pwo, HH*HH);
    pack_h<<<(FFF*HH)/2048, 256>>>(W1, pw1, FFF*HH);
    pack_h<<<(ADD*HH)/2048, 256>>>(Wad, pwad, ADD*HH);
    pack_h_pitch<<<(HH*FFF)/2048, 256>>>(W2,  pw2c,       HH, FFF, FAK);
    pack_h_pitch<<<(HH*ADD)/2048, 256>>>(Wau, pw2c + FFF, HH, ADD, FAK);
    cudaMemcpyAsync(pbqkv,        bq, HH*4, cudaMemcpyDeviceToDevice, 0);
    cudaMemcpyAsync(pbqkv + HH,   bk, HH*4, cudaMemcpyDeviceToDevice, 0);
    cudaMemcpyAsync(pbqkv + 2*HH, bv, HH*4, cudaMemcpyDeviceToDevice, 0);
    bias_sum<<<4, 256>>>(b2, bau, pb2c, HH);

    // 1) relative position bias table
    pbias_kernel<<<(2047 + 127) / 128, 128>>>(rel, ppb);
    // 2) gates
    gate_kernel<<<BB * SS, 128>>>(x, Wg, bg, gru, pgate);
    // 3) fused QKV projection -> packed [M,3072] half
    gemm_h<0,1><<<dim3(QKVN/128, MM/128), 256, HS_BYTES>>>(pxr, pwqkv, pbqkv, pqkv, MM, QKVN, HH, QKVN);
    // 4) attention
    attn_tc<<<dim3(SS/64, NHH, BB), 128, ATT_BYTES>>>(pqkv, pgate, ppb, pctx);
    // 5) output projection (float out)
    gemm_h<0,0><<<dim3(HH/128, MM/128), 256, HS_BYTES>>>(pctx, pwo, bo, patt, MM, HH, HH, HH);
    // 6) residual + LN1 (fp32 h + fp16 copy)
    ln_kernel<<<MM, 256>>>(x, patt, l1g, l1b, ph, phr);
    // 7) FFN up (gelu) + adapter down (elu) into [M,4352] half
    gemm_h<1,1><<<dim3(FFF/128, MM/128), 256, HS_BYTES>>>(phr, pw1, b1, pff1, MM, FFF, HH, FAK);
    gemm_h<2,1><<<dim3(ADD/128, MM/128), 256, HS_BYTES>>>(phr, pwad, bad, pff1 + FFF, MM, ADD, HH, FAK);
    // 8) fused FFN down + adapter up
    gemm_h<0,0><<<dim3(HH/128, MM/128), 256, HS_BYTES>>>(pff1, pw2c, pb2c, pff2, MM, HH, FAK, HH);
    // 9) h + (ff+adapt), LN2 -> out
    ln_kernel<<<MM, 256>>>(ph, pff2, l2g, l2b, out, nullptr);
}

// round 7
// speedup vs baseline: 5.4627x; 1.0349x over previous
#include <cuda_runtime.h>
#include <cuda_fp16.h>
#include <math.h>
#include <stdint.h>

// ---------------- problem constants ----------------
#define BB   4
#define SS   1024
#define HH   1024
#define NHH  16
#define HDD  64
#define FFF  4096
#define ADD  256
#define MM   (BB*SS)          // 4096 rows
#define EPSF 1e-5f
#define QKVN 3072
#define FAK  (FFF+ADD)        // 4352

// ---------------- scratch ----------------
__device__ __half g_qkv [(size_t)MM*QKVN];
__device__ __half g_ctx [MM*HH];
__device__ float  g_att [MM*HH];
__device__ float  g_h   [MM*HH];
__device__ __half g_hr  [MM*HH];
__device__ __half g_ff1 [(size_t)MM*FAK];
__device__ float  g_ff2 [MM*HH];
__device__ float  g_gate[BB*NHH*SS];
__device__ float  g_pb  [NHH*2048];
// fp16 operand copies
__device__ __half g_xr  [MM*HH];
__device__ __half g_wqkv[QKVN*HH];
__device__ __half g_wo  [HH*HH];
__device__ __half g_w1  [(size_t)FFF*HH];
__device__ __half g_w2c [(size_t)HH*FAK];
__device__ __half g_wad [ADD*HH];
__device__ float  g_bqkv[QKVN];
__device__ float  g_b2c [HH];

// ---------------- helpers ----------------
__device__ __forceinline__ uint32_t smem_u32(const void* p) {
    uint32_t a;
    asm("{ .reg .u64 t; cvta.to.shared.u64 t, %1; cvt.u32.u64 %0, t; }" : "=r"(a) : "l"(p));
    return a;
}
__device__ __forceinline__ void cp16(uint32_t s, const void* g) {
    asm volatile("cp.async.cg.shared.global [%0], [%1], 16;" :: "r"(s), "l"(g));
}
#define CP_COMMIT() asm volatile("cp.async.commit_group;")
#define CP_WAIT(N)  asm volatile("cp.async.wait_group %0;" :: "n"(N))

__device__ __forceinline__ void mma_f16(float& c0, float& c1, float& c2, float& c3,
                                        uint32_t a0, uint32_t a1, uint32_t a2, uint32_t a3,
                                        uint32_t b0, uint32_t b1) {
    asm volatile(
        "mma.sync.aligned.m16n8k16.row.col.f32.f16.f16.f32 "
        "{%0,%1,%2,%3}, {%4,%5,%6,%7}, {%8,%9}, {%0,%1,%2,%3};\n"
        : "+f"(c0), "+f"(c1), "+f"(c2), "+f"(c3)
        : "r"(a0), "r"(a1), "r"(a2), "r"(a3), "r"(b0), "r"(b1));
}
__device__ __forceinline__ void ldsm_x4(uint32_t& r0, uint32_t& r1, uint32_t& r2, uint32_t& r3,
                                        uint32_t addr) {
    asm volatile("ldmatrix.sync.aligned.m8n8.x4.shared.b16 {%0,%1,%2,%3}, [%4];"
                 : "=r"(r0), "=r"(r1), "=r"(r2), "=r"(r3) : "r"(addr));
}
__device__ __forceinline__ void ldsm_x2(uint32_t& r0, uint32_t& r1, uint32_t addr) {
    asm volatile("ldmatrix.sync.aligned.m8n8.x2.shared.b16 {%0,%1}, [%2];"
                 : "=r"(r0), "=r"(r1) : "r"(addr));
}
__device__ __forceinline__ void ldsm_x2_trans(uint32_t& b0, uint32_t& b1, uint32_t addr) {
    asm volatile("ldmatrix.sync.aligned.m8n8.x2.trans.shared.b16 {%0,%1}, [%2];"
                 : "=r"(b0), "=r"(b1) : "r"(addr));
}
__device__ __forceinline__ uint32_t packh2(float a, float b) {
    __half2 h = __floats2half2_rn(a, b);
    return *(uint32_t*)&h;
}

// ---------------- f32 -> f16 pack ----------------
__global__ void pack_h(const float* __restrict__ in, __half* __restrict__ out, int n)
{
    int i = (blockIdx.x * 256 + threadIdx.x) * 8;
    if (i >= n) return;
    float4 a = *(const float4*)(in + i);
    float4 b = *(const float4*)(in + i + 4);
    uint4 o;
    o.x = packh2(a.x, a.y); o.y = packh2(a.z, a.w);
    o.z = packh2(b.x, b.y); o.w = packh2(b.z, b.w);
    *(uint4*)(out + i) = o;
}
__global__ void pack_h_pitch(const float* __restrict__ in, __half* __restrict__ out,
                             int rows, int cols, int ldo)
{
    int i = (blockIdx.x * 256 + threadIdx.x) * 8;
    if (i >= rows * cols) return;
    int row = i / cols, col = i - row * cols;
    float4 a = *(const float4*)(in + (size_t)row * cols + col);
    float4 b = *(const float4*)(in + (size_t)row * cols + col + 4);
    uint4 o;
    o.x = packh2(a.x, a.y); o.y = packh2(a.z, a.w);
    o.z = packh2(b.x, b.y); o.w = packh2(b.z, b.w);
    *(uint4*)(out + (size_t)row * ldo + col) = o;
}
__global__ void bias_sum(const float* __restrict__ a, const float* __restrict__ b,
                         float* __restrict__ o, int n)
{
    int i = blockIdx.x * 256 + threadIdx.x;
    if (i < n) o[i] = a[i] + b[i];
}

// ================= fp16 mma.sync GEMM: ldmatrix + 3-stage cp.async =================
// A[M,K], W[N,K] half; C = A @ W^T + bias. BM=BN=128, BK=32.
#define HS_STRIDE 20
#define HS_AWORDS (128*HS_STRIDE)
#define HS_STAGEW (2*HS_AWORDS)
#define HS_BYTES  (3*HS_STAGEW*4)   // 61440

template<int EPI, int OUTH>   // EPI: 0=none,1=gelu,2=elu ; OUTH: 1=half out, 0=float out
__global__ void __launch_bounds__(256, 2) gemm_h(const __half* __restrict__ A,
                                                 const __half* __restrict__ W,
                                                 const float* __restrict__ bias,
                                                 void* __restrict__ C,
                                                 int M, int N, int K, int ldc)
{
    extern __shared__ uint32_t sm[];
    int tid  = threadIdx.x;
    int wid  = tid >> 5, lane = tid & 31;
    int wm   = wid >> 2;          // 0..1
    int wn   = wid & 3;           // 0..3
    int bm = blockIdx.y * 128, bn = blockIdx.x * 128;
    int r4 = lane >> 2;
    int c4 = lane & 3;

    float acc[4][4][4];
    #pragma unroll
    for (int mt = 0; mt < 4; mt++)
        #pragma unroll
        for (int nt = 0; nt < 4; nt++)
            #pragma unroll
            for (int u = 0; u < 4; u++) acc[mt][nt][u] = 0.0f;

    // producer addressing
    int lrow = tid >> 2;            // 0..63
    int lcc  = tid & 3;             // 16B chunk
    const __half* aptr = A + (size_t)(bm + lrow) * K + lcc * 8;
    const __half* wptr = W + (size_t)(bn + lrow) * K + lcc * 8;
    uint32_t sb = smem_u32(sm);
    uint32_t sa_base = sb + (uint32_t)(lrow * HS_STRIDE + lcc * 4) * 4;

    // consumer ldmatrix lane addresses (byte offsets within a stage)
    uint32_t aoff = (uint32_t)((wm * 64 + (lane & 15)) * HS_STRIDE) * 4 + ((lane >> 4) << 3) * 2;
    uint32_t boff = (uint32_t)(HS_AWORDS * 4)
                  + (uint32_t)((wn * 32 + (lane & 7)) * HS_STRIDE) * 4 + (((lane >> 3) & 1) << 3) * 2;

    int T = K >> 5;

    // prologue: tiles 0,1 -> stages 0,1
    #pragma unroll
    for (int t0 = 0; t0 < 2; t0++) {
        const __half* ap = aptr + t0 * 32;
        const __half* wp = wptr + t0 * 32;
        uint32_t so = sa_base + (uint32_t)(t0 * HS_STAGEW) * 4;
        #pragma unroll
        for (int i = 0; i < 2; i++) {
            cp16(so + (uint32_t)(i * 64 * HS_STRIDE) * 4, ap + (size_t)(i * 64) * K);
            cp16(so + (uint32_t)(HS_AWORDS + i * 64 * HS_STRIDE) * 4, wp + (size_t)(i * 64) * K);
        }
        CP_COMMIT();
    }

    int stage = 0;
    for (int k0 = 0; k0 < T; k0++) {
        // wait for tile k0 (tile k0+1 may still be in flight)
        if (k0 + 1 < T) { CP_WAIT(1); } else { CP_WAIT(0); }
        __syncthreads();   // stage data visible; all warps done with stage being overwritten next
        if (k0 + 2 < T) {
            int ns = stage + 2; if (ns >= 3) ns -= 3;
            const __half* ap = aptr + (k0 + 2) * 32;
            const __half* wp = wptr + (k0 + 2) * 32;
            uint32_t so = sa_base + (uint32_t)(ns * HS_STAGEW) * 4;
            #pragma unroll
            for (int i = 0; i < 2; i++) {
                cp16(so + (uint32_t)(i * 64 * HS_STRIDE) * 4, ap + (size_t)(i * 64) * K);
                cp16(so + (uint32_t)(HS_AWORDS + i * 64 * HS_STRIDE) * 4, wp + (size_t)(i * 64) * K);
            }
            CP_COMMIT();
        }
        uint32_t stg = sb + (uint32_t)(stage * HS_STAGEW) * 4;
        #pragma unroll
        for (int ks = 0; ks < 2; ks++) {       // two k16 steps
            uint32_t af[4][4];
            #pragma unroll
            for (int mt = 0; mt < 4; mt++)
                ldsm_x4(af[mt][0], af[mt][1], af[mt][2], af[mt][3],
                        stg + aoff + (uint32_t)(mt * 16 * HS_STRIDE) * 4 + ks * 32);
            uint32_t bf[4][2];
            #pragma unroll
            for (int nt = 0; nt < 4; nt++)
                ldsm_x2(bf[nt][0], bf[nt][1],
                        stg + boff + (uint32_t)(nt * 8 * HS_STRIDE) * 4 + ks * 32);
            #pragma unroll
            for (int mt = 0; mt < 4; mt++)
                #pragma unroll
                for (int nt = 0; nt < 4; nt++)
                    mma_f16(acc[mt][nt][0], acc[mt][nt][1], acc[mt][nt][2], acc[mt][nt][3],
                            af[mt][0], af[mt][1], af[mt][2], af[mt][3],
                            bf[nt][0], bf[nt][1]);
        }
        stage++; if (stage == 3) stage = 0;
    }

    // ---- epilogue ----
    #pragma unroll
    for (int mt = 0; mt < 4; mt++) {
        int gr = bm + wm * 64 + mt * 16 + r4;
        #pragma unroll
        for (int nt = 0; nt < 4; nt++) {
            int gc = bn + wn * 32 + nt * 8 + c4 * 2;
            float b0 = bias[gc], b1 = bias[gc + 1];
            float v[4];
            v[0] = acc[mt][nt][0] + b0;
            v[1] = acc[mt][nt][1] + b1;
            v[2] = acc[mt][nt][2] + b0;
            v[3] = acc[mt][nt][3] + b1;
            #pragma unroll
            for (int u = 0; u < 4; u++) {
                if (EPI == 1) v[u] = 0.5f * v[u] * (1.0f + erff(v[u] * 0.7071067811865476f));
                else if (EPI == 2) v[u] = v[u] > 0.0f ? v[u] : expm1f(v[u]);
            }
            if (OUTH) {
                __half* Ch = (__half*)C;
                *(uint32_t*)(Ch + (size_t)gr * ldc + gc)       = packh2(v[0], v[1]);
                *(uint32_t*)(Ch + (size_t)(gr + 8) * ldc + gc) = packh2(v[2], v[3]);
            } else {
                float* Cf = (float*)C;
                *(float2*)(Cf + (size_t)gr * ldc + gc)       = make_float2(v[0], v[1]);
                *(float2*)(Cf + (size_t)(gr + 8) * ldc + gc) = make_float2(v[2], v[3]);
            }
        }
    }
}

// ---------------- relative position bias table ----------------
__global__ void pbias_kernel(const float* __restrict__ rel_embed, float* __restrict__ pb)
{
    int d = blockIdx.x * blockDim.x + threadIdx.x;
    if (d >= 2047) return;
    int rel = d - 1023;
    int bucket = (rel > 0) ? 160 : 0;
    int r = rel < 0 ? -rel : rel;
    int val;
    if (r < 80) {
        val = r;
    } else {
        float rf = (float)(r < 1 ? 1 : r);
        float t = logf(rf / 80.0f) / 2.3025851f * 80.0f;
        int large = 80 + (int)t;
        val = large < 159 ? large : 159;
    }
    bucket += val;
    #pragma unroll
    for (int h = 0; h < NHH; h++)
        pb[h * 2048 + d] = rel_embed[bucket * NHH + h];
}

// ---------------- gate kernel ----------------
__global__ void gate_kernel(const float* __restrict__ x, const float* __restrict__ Wg,
                            const float* __restrict__ bg, const float* __restrict__ gc,
                            float* __restrict__ gate)
{
    __shared__ float xs[HH];
    int bs = blockIdx.x;
    int t = threadIdx.x;
    for (int i = t; i < HH; i += 128) xs[i] = x[(size_t)bs * HH + i];
    __syncthreads();
    int h = t >> 3, e = t & 7;
    float acc = bg[e];
    const float* wrow = Wg + e * HDD;
    const float* xrow = xs + h * HDD;
    #pragma unroll 8
    for (int d = 0; d < HDD; d++) acc += xrow[d] * wrow[d];
    acc += __shfl_xor_sync(0xffffffffu, acc, 1);
    acc += __shfl_xor_sync(0xffffffffu, acc, 2);
    float other = __shfl_xor_sync(0xffffffffu, acc, 4);
    if (e == 0) {
        float p0 = acc, p1 = other;
        float ga = 1.0f / (1.0f + expf(-p0));
        float gb = 1.0f / (1.0f + expf(-p1));
        float go = ga * (gb * gc[h] - 1.0f) + 2.0f;
        int b = bs >> 10, s = bs & 1023;
        gate[(b * NHH + h) * SS + s] = go;
    }
}

// ================= fp16 tensor-core flash attention =================
#define AS 36
#define ATT_WORDS (4*64*AS)
#define ATT_BYTES (ATT_WORDS*4)    // 36864

__global__ void __launch_bounds__(128, 3) attn_tc(const __half* __restrict__ qkv,
                                                  const float* __restrict__ gate,
                                                  const float* __restrict__ pb,
                                                  __half* __restrict__ ctx)
{
    extern __shared__ uint32_t as_[];
    uint32_t* Qs = as_;
    uint32_t* Ks = Qs + 64 * AS;
    uint32_t* Ps = Ks + 64 * AS;
    uint32_t* Vs = Ps + 64 * AS;

    int tid = threadIdx.x, wid = tid >> 5, lane = tid & 31;
    int r4 = lane >> 2, c4 = lane & 3;
    int i0 = blockIdx.x * 64, h = blockIdx.y, b = blockIdx.z;

    const __half* qb = qkv + ((size_t)(b * SS + i0)) * QKVN + h * HDD;
    const __half* kb = qkv + ((size_t)(b * SS)) * QKVN + HH + h * HDD;
    const __half* vb = qkv + ((size_t)(b * SS)) * QKVN + 2 * HH + h * HDD;

    for (int idx = tid; idx < 64 * 8; idx += 128) {
        int r = idx >> 3, cc = idx & 7;
        *(uint4*)(Qs + r * AS + cc * 4) = *(const uint4*)(qb + (size_t)r * QKVN + cc * 8);
    }
    __syncthreads();

    uint32_t qf[4][4];
    {
        const uint32_t* qp = Qs + (wid * 16 + r4) * AS + c4;
        #pragma unroll
        for (int ks = 0; ks < 4; ks++) {
            qf[ks][0] = qp[ks * 8];
            qf[ks][1] = qp[8 * AS + ks * 8];
            qf[ks][2] = qp[ks * 8 + 4];
            qf[ks][3] = qp[8 * AS + ks * 8 + 4];
        }
    }

    float gate0 = gate[(b * NHH + h) * SS + i0 + wid * 16 + r4];
    float gate1 = gate[(b * NHH + h) * SS + i0 + wid * 16 + r4 + 8];
    const float* pbh = pb + h * 2048 + 1023 - (i0 + wid * 16 + r4);

    float m0 = -INFINITY, m1 = -INFINITY, l0 = 0.0f, l1 = 0.0f;
    float oa[8][4];
    #pragma unroll
    for (int nt = 0; nt < 8; nt++)
        #pragma unroll
        for (int u = 0; u < 4; u++) oa[nt][u] = 0.0f;

    uint32_t ksm = smem_u32(Ks);
    uint32_t vsm = smem_u32(Vs);
    uint32_t vls = vsm + (uint32_t)(lane & 15) * AS * 4;

    for (int j0 = 0; j0 < SS; j0 += 64) {
        __syncthreads();
        for (int idx = tid; idx < 64 * 8; idx += 128) {
            int r = idx >> 3, cc = idx & 7;
            cp16(ksm + (uint32_t)(r * AS + cc * 4) * 4, kb + (size_t)(j0 + r) * QKVN + cc * 8);
            cp16(vsm + (uint32_t)(r * AS + cc * 4) * 4, vb + (size_t)(j0 + r) * QKVN + cc * 8);
        }
        CP_COMMIT();
        CP_WAIT(0);
        __syncthreads();

        float sf[8][4];
        #pragma unroll
        for (int nt = 0; nt < 8; nt++)
            #pragma unroll
            for (int u = 0; u < 4; u++) sf[nt][u] = 0.0f;
        #pragma unroll
        for (int ks = 0; ks < 4; ks++) {
            #pragma unroll
            for (int nt = 0; nt < 8; nt++) {
                const uint32_t* p = Ks + (nt * 8 + r4) * AS + ks * 8 + c4;
                mma_f16(sf[nt][0], sf[nt][1], sf[nt][2], sf[nt][3],
                        qf[ks][0], qf[ks][1], qf[ks][2], qf[ks][3],
                        p[0], p[4]);
            }
        }

        #pragma unroll
        for (int nt = 0; nt < 8; nt++) {
            int j = j0 + nt * 8 + 2 * c4;
            float pb0 = pbh[j];
            float pb1 = pbh[j + 1];
            float pb2 = pbh[j - 8];
            float pb3 = pbh[j - 7];
            sf[nt][0] = sf[nt][0] * 0.125f + gate0 * pb0;
            sf[nt][1] = sf[nt][1] * 0.125f + gate0 * pb1;
            sf[nt][2] = sf[nt][2] * 0.125f + gate1 * pb2;
            sf[nt][3] = sf[nt][3] * 0.125f + gate1 * pb3;
        }

        float mx0 = -INFINITY, mx1 = -INFINITY;
        #pragma unroll
        for (int nt = 0; nt < 8; nt++) {
            mx0 = fmaxf(mx0, fmaxf(sf[nt][0], sf[nt][1]));
            mx1 = fmaxf(mx1, fmaxf(sf[nt][2], sf[nt][3]));
        }
        mx0 = fmaxf(mx0, __shfl_xor_sync(0xffffffffu, mx0, 1));
        mx0 = fmaxf(mx0, __shfl_xor_sync(0xffffffffu, mx0, 2));
        mx1 = fmaxf(mx1, __shfl_xor_sync(0xffffffffu, mx1, 1));
        mx1 = fmaxf(mx1, __shfl_xor_sync(0xffffffffu, mx1, 2));
        float mn0 = fmaxf(m0, mx0), mn1 = fmaxf(m1, mx1);
        float a0 = __expf(m0 - mn0), a1 = __expf(m1 - mn1);

        float ls0 = 0.0f, ls1 = 0.0f;
        uint32_t* pr0 = Ps + (wid * 16 + r4) * AS + c4;
        uint32_t* pr1 = pr0 + 8 * AS;
        #pragma unroll
        for (int nt = 0; nt < 8; nt++) {
            float p0 = __expf(sf[nt][0] - mn0);
            float p1 = __expf(sf[nt][1] - mn0);
            float p2 = __expf(sf[nt][2] - mn1);
            float p3 = __expf(sf[nt][3] - mn1);
            ls0 += p0 + p1; ls1 += p2 + p3;
            pr0[nt * 4] = packh2(p0, p1);
            pr1[nt * 4] = packh2(p2, p3);
        }
        ls0 += __shfl_xor_sync(0xffffffffu, ls0, 1);
        ls0 += __shfl_xor_sync(0xffffffffu, ls0, 2);
        ls1 += __shfl_xor_sync(0xffffffffu, ls1, 1);
        ls1 += __shfl_xor_sync(0xffffffffu, ls1, 2);
        l0 = l0 * a0 + ls0;  l1 = l1 * a1 + ls1;
        m0 = mn0;  m1 = mn1;
        #pragma unroll
        for (int nt = 0; nt < 8; nt++) {
            oa[nt][0] *= a0; oa[nt][1] *= a0;
            oa[nt][2] *= a1; oa[nt][3] *= a1;
        }
        __syncwarp();

        const uint32_t* pp = Ps + (wid * 16 + r4) * AS + c4;
        #pragma unroll
        for (int ks = 0; ks < 4; ks++) {
            uint32_t af0 = pp[ks * 8];
            uint32_t af1 = pp[8 * AS + ks * 8];
            uint32_t af2 = pp[ks * 8 + 4];
            uint32_t af3 = pp[8 * AS + ks * 8 + 4];
            uint32_t vrow = vls + (uint32_t)(ks * 16) * AS * 4;
            #pragma unroll
            for (int nt = 0; nt < 8; nt++) {
                uint32_t b0, b1;
                ldsm_x2_trans(b0, b1, vrow + nt * 16);
                mma_f16(oa[nt][0], oa[nt][1], oa[nt][2], oa[nt][3],
                        af0, af1, af2, af3, b0, b1);
            }
        }
    }

    float inv0 = 1.0f / l0, inv1 = 1.0f / l1;
    __half* cb0 = ctx + ((size_t)(b * SS + i0 + wid * 16 + r4)) * HH + h * HDD;
    __half* cb1 = cb0 + 8 * HH;
    #pragma unroll
    for (int nt = 0; nt < 8; nt++) {
        *(uint32_t*)(cb0 + nt * 8 + 2 * c4) = packh2(oa[nt][0] * inv0, oa[nt][1] * inv0);
        *(uint32_t*)(cb1 + nt * 8 + 2 * c4) = packh2(oa[nt][2] * inv1, oa[nt][3] * inv1);
    }
}

// ---------------- residual-add + LayerNorm (+ optional half copy) ----------------
__global__ void ln_kernel(const float* __restrict__ A, const float* __restrict__ B,
                          const float* __restrict__ g, const float* __restrict__ bt,
                          float* __restrict__ out, __half* __restrict__ out2)
{
    __shared__ float sm[8];
    int row = blockIdx.x;
    int t = threadIdx.x;
    size_t base = (size_t)row * HH;
    float vals[4];
    #pragma unroll
    for (int u = 0; u < 4; u++) {
        int i = t + u*256;
        vals[u] = A[base + i] + B[base + i];
    }
    float sum = vals[0] + vals[1] + vals[2] + vals[3];
    #pragma unroll
    for (int off = 16; off >= 1; off >>= 1) sum += __shfl_xor_sync(0xffffffffu, sum, off);
    if ((t & 31) == 0) sm[t >> 5] = sum;
    __syncthreads();
    float tot = 0.0f;
    #pragma unroll
    for (int w = 0; w < 8; w++) tot += sm[w];
    float mean = tot * (1.0f / HH);
    __syncthreads();
    float vs = 0.0f;
    #pragma unroll
    for (int u = 0; u < 4; u++) { float d = vals[u] - mean; vs += d * d; }
    #pragma unroll
    for (int off = 16; off >= 1; off >>= 1) vs += __shfl_xor_sync(0xffffffffu, vs, off);
    if ((t & 31) == 0) sm[t >> 5] = vs;
    __syncthreads();
    float vtot = 0.0f;
    #pragma unroll
    for (int w = 0; w < 8; w++) vtot += sm[w];
    float rstd = rsqrtf(vtot * (1.0f / HH) + EPSF);
    #pragma unroll
    for (int u = 0; u < 4; u++) {
        int i = t + u*256;
        float r = (vals[u] - mean) * rstd * g[i] + bt[i];
        out[base + i] = r;
        if (out2) out2[base + i] = __float2half_rn(r);
    }
}

// ---------------- launch ----------------
extern "C" void kernel_launch(void* const* d_in, const int* in_sizes, int n_in,
                              void* d_out, int out_size)
{
    const float* x   = (const float*)d_in[0];
    const float* Wq  = (const float*)d_in[1];
    const float* bq  = (const float*)d_in[2];
    const float* Wk  = (const float*)d_in[3];
    const float* bk  = (const float*)d_in[4];
    const float* Wv  = (const float*)d_in[5];
    const float* bv  = (const float*)d_in[6];
    const float* Wo  = (const float*)d_in[7];
    const float* bo  = (const float*)d_in[8];
    const float* Wg  = (const float*)d_in[9];
    const float* bg  = (const float*)d_in[10];
    const float* gru = (const float*)d_in[11];
    const float* rel = (const float*)d_in[12];
    const float* l1g = (const float*)d_in[13];
    const float* l1b = (const float*)d_in[14];
    const float* W1  = (const float*)d_in[15];
    const float* b1  = (const float*)d_in[16];
    const float* W2  = (const float*)d_in[17];
    const float* b2  = (const float*)d_in[18];
    const float* l2g = (const float*)d_in[19];
    const float* l2b = (const float*)d_in[20];
    const float* Wad = (const float*)d_in[21];
    const float* bad = (const float*)d_in[22];
    const float* Wau = (const float*)d_in[23];
    const float* bau = (const float*)d_in[24];
    float* out = (float*)d_out;

    __half *pqkv, *pctx, *phr, *pff1, *pxr, *pwqkv, *pwo, *pw1, *pw2c, *pwad;
    float *patt, *ph, *pff2, *pgate, *ppb, *pbqkv, *pb2c;
    cudaGetSymbolAddress((void**)&pqkv, g_qkv);
    cudaGetSymbolAddress((void**)&pctx, g_ctx);
    cudaGetSymbolAddress((void**)&patt, g_att);
    cudaGetSymbolAddress((void**)&ph,   g_h);
    cudaGetSymbolAddress((void**)&phr,  g_hr);
    cudaGetSymbolAddress((void**)&pff1, g_ff1);
    cudaGetSymbolAddress((void**)&pff2, g_ff2);
    cudaGetSymbolAddress((void**)&pgate, g_gate);
    cudaGetSymbolAddress((void**)&ppb,  g_pb);
    cudaGetSymbolAddress((void**)&pxr,  g_xr);
    cudaGetSymbolAddress((void**)&pwqkv, g_wqkv);
    cudaGetSymbolAddress((void**)&pwo,  g_wo);
    cudaGetSymbolAddress((void**)&pw1,  g_w1);
    cudaGetSymbolAddress((void**)&pw2c, g_w2c);
    cudaGetSymbolAddress((void**)&pwad, g_wad);
    cudaGetSymbolAddress((void**)&pbqkv, g_bqkv);
    cudaGetSymbolAddress((void**)&pb2c, g_b2c);

    cudaFuncSetAttribute(gemm_h<0,0>, cudaFuncAttributeMaxDynamicSharedMemorySize, HS_BYTES);
    cudaFuncSetAttribute(gemm_h<0,1>, cudaFuncAttributeMaxDynamicSharedMemorySize, HS_BYTES);
    cudaFuncSetAttribute(gemm_h<1,1>, cudaFuncAttributeMaxDynamicSharedMemorySize, HS_BYTES);
    cudaFuncSetAttribute(gemm_h<2,1>, cudaFuncAttributeMaxDynamicSharedMemorySize, HS_BYTES);
    cudaFuncSetAttribute(attn_tc, cudaFuncAttributeMaxDynamicSharedMemorySize, ATT_BYTES);

    // 0) pack all GEMM operands to fp16
    pack_h<<<(MM*HH)/2048, 256>>>(x,  pxr, MM*HH);
    pack_h<<<(HH*HH)/2048, 256>>>(Wq, pwqkv,           HH*HH);
    pack_h<<<(HH*HH)/2048, 256>>>(Wk, pwqkv + HH*HH,   HH*HH);
    pack_h<<<(HH*HH)/2048, 256>>>(Wv, pwqkv + 2*HH*HH, HH*HH);
    pack_h<<<(HH*HH)/2048, 256>>>(Wo, pwo, HH*HH);
    pack_h<<<(FFF*HH)/2048, 256>>>(W1, pw1, FFF*HH);
    pack_h<<<(ADD*HH)/2048, 256>>>(Wad, pwad, ADD*HH);
    pack_h_pitch<<<(HH*FFF)/2048, 256>>>(W2,  pw2c,       HH, FFF, FAK);
    pack_h_pitch<<<(HH*ADD)/2048, 256>>>(Wau, pw2c + FFF, HH, ADD, FAK);
    cudaMemcpyAsync(pbqkv,        bq, HH*4, cudaMemcpyDeviceToDevice, 0);
    cudaMemcpyAsync(pbqkv + HH,   bk, HH*4, cudaMemcpyDeviceToDevice, 0);
    cudaMemcpyAsync(pbqkv + 2*HH, bv, HH*4, cudaMemcpyDeviceToDevice, 0);
    bias_sum<<<4, 256>>>(b2, bau, pb2c, HH);

    // 1) relative position bias table
    pbias_kernel<<<(2047 + 127) / 128, 128>>>(rel, ppb);
    // 2) gates
    gate_kernel<<<BB * SS, 128>>>(x, Wg, bg, gru, pgate);
    // 3) fused QKV projection -> packed [M,3072] half
    gemm_h<0,1><<<dim3(QKVN/128, MM/128), 256, HS_BYTES>>>(pxr, pwqkv, pbqkv, pqkv, MM, QKVN, HH, QKVN);
    // 4) attention
    attn_tc<<<dim3(SS/64, NHH, BB), 128, ATT_BYTES>>>(pqkv, pgate, ppb, pctx);
    // 5) output projection (float out)
    gemm_h<0,0><<<dim3(HH/128, MM/128), 256, HS_BYTES>>>(pctx, pwo, bo, patt, MM, HH, HH, HH);
    // 6) residual + LN1 (fp32 h + fp16 copy)
    ln_kernel<<<MM, 256>>>(x, patt, l1g, l1b, ph, phr);
    // 7) FFN up (gelu) + adapter down (elu) into [M,4352] half
    gemm_h<1,1><<<dim3(FFF/128, MM/128), 256, HS_BYTES>>>(phr, pw1, b1, pff1, MM, FFF, HH, FAK);
    gemm_h<2,1><<<dim3(ADD/128, MM/128), 256, HS_BYTES>>>(phr, pwad, bad, pff1 + FFF, MM, ADD, HH, FAK);
    // 8) fused FFN down + adapter up
    gemm_h<0,0><<<dim3(HH/128, MM/128), 256, HS_BYTES>>>(pff1, pw2c, pb2c, pff2, MM, HH, FAK, HH);
    // 9) h + (ff+adapt), LN2 -> out
    ln_kernel<<<MM, 256>>>(ph, pff2, l2g, l2b, out, nullptr);
}